// round 2
// baseline (speedup 1.0000x reference)
#include <cuda_runtime.h>
#include <cuda_bf16.h>
#include <cstdint>

// =============================================================================
// MoE fused layer on plain sm_103 target (no 'a' features available from this
// toolchain -> tcgen05 rejected by ptxas). Tensor path: legacy mma.sync tf32
// (m16n8k8) with cp.async double-buffered pipeline.
// T=4096, D=1024, E=8, K=2, F=SF=1024 (all inner dims 1024, hardcoded).
// =============================================================================

#define NEXP   8
#define NTOK   4096
#define NROWS  8192
#define CPE    1024

// ---------------- scratch (device globals: allocation-free rule) ------------
__device__ float g_H [8192u * 1024u];   // routed: U then H=silu(G)*U (in place)
__device__ float g_Y [8192u * 1024u];   // routed down output (permuted order)
__device__ float g_SH[4096u * 1024u];   // shared: SU then SH=silu(SG)*SU
__device__ float g_S [4096u * 1024u];   // shared down output
__device__ int   g_perm[8192];          // permuted row -> flat (t*K+k)
__device__ int   g_inv [8192];          // flat -> permuted row

// ---------------- helpers ----------------------------------------------------
__device__ __forceinline__ uint32_t smem_u32(const void* p) {
    uint32_t a;
    asm("{ .reg .u64 t; cvta.to.shared.u64 t, %1; cvt.u32.u64 %0, t; }"
        : "=r"(a) : "l"(p));
    return a;
}

__device__ __forceinline__ void cp_async16(uint32_t dst, const void* src) {
    asm volatile("cp.async.cg.shared.global [%0], [%1], 16;"
                 :: "r"(dst), "l"(src) : "memory");
}
__device__ __forceinline__ void cp_commit() {
    asm volatile("cp.async.commit_group;" ::: "memory");
}
template<int N>
__device__ __forceinline__ void cp_wait() {
    asm volatile("cp.async.wait_group %0;" :: "n"(N) : "memory");
}

__device__ __forceinline__ uint32_t f2tf32(float f) {
    uint32_t r;
    asm("cvt.rna.tf32.f32 %0, %1;" : "=r"(r) : "f"(f));
    return r;
}

__device__ __forceinline__ void mma_tf32(float* d, const uint32_t* a,
                                         const uint32_t* b) {
    asm volatile(
        "mma.sync.aligned.m16n8k8.row.col.f32.tf32.tf32.f32 "
        "{%0,%1,%2,%3}, {%4,%5,%6,%7}, {%8,%9}, {%0,%1,%2,%3};"
        : "+f"(d[0]), "+f"(d[1]), "+f"(d[2]), "+f"(d[3])
        : "r"(a[0]), "r"(a[1]), "r"(a[2]), "r"(a[3]), "r"(b[0]), "r"(b[1]));
}

__device__ __forceinline__ float silu(float x) {
    return x / (1.f + __expf(-x));
}

// =============================================================================
// Stable counting-sort permutation (matches jnp.argsort stability).
// =============================================================================
__global__ void build_perm_kernel(const int* __restrict__ tki) {
    const int e = blockIdx.x;
    const int tid = threadIdx.x;
    __shared__ int scan[256];
    __shared__ int basev;
    if (tid == 0) basev = 0;
    __syncthreads();
    for (int start = 0; start < NROWS; start += 256) {
        const int i = start + tid;
        const int m = (tki[i] == e) ? 1 : 0;
        scan[tid] = m;
        __syncthreads();
        #pragma unroll
        for (int off = 1; off < 256; off <<= 1) {
            int v = (tid >= off) ? scan[tid - off] : 0;
            __syncthreads();
            scan[tid] += v;
            __syncthreads();
        }
        if (m) {
            const int dest = e * CPE + basev + scan[tid] - 1;
            g_perm[dest] = i;
            g_inv[i] = dest;
        }
        __syncthreads();
        if (tid == 0) basev += scan[255];
        __syncthreads();
    }
}

// =============================================================================
// tf32 mma.sync GEMM: CTA tile 128x128x(K=1024 in 32-chunks), 8 warps,
// warp tile 32x64 (2 m-frags x 8 n-frags of m16n8k8), cp.async 2-stage.
//   A: [M,1024] row-major, optionally gathered (routed path).
//   B: [1024,1024] N-contiguous (weights); expert z offsets by 1M elements.
//   EPI 0: Out = D.     EPI 1: Out = silu(D) * Aux   (Aux may alias Out).
// smem per stage: A 128x36 f32 (18432 B) + B 32x132 f32 (16896 B) = 35328 B.
// =============================================================================
#define STG_BYTES 35328
#define A_STRIDE  36
#define B_STRIDE  132

template<bool GATHER, int EPI>
__global__ void __launch_bounds__(256, 2) gemm_mma(
    const float* __restrict__ A,
    const float* __restrict__ Bg,
    const float* __restrict__ Aux,
    float* __restrict__ Out)
{
    extern __shared__ char sm[];
    const uint32_t smem = smem_u32(sm);
    int* srcRow = (int*)(sm + 2 * STG_BYTES);

    const int tid  = threadIdx.x;
    const int wid  = tid >> 5;
    const int lane = tid & 31;
    const int wm   = wid & 3;          // warp m index (0..3)
    const int wn   = wid >> 2;         // warp n index (0..1)
    const int row4 = lane >> 2;        // 0..7
    const int kq   = lane & 3;         // 0..3

    const int mBase = (blockIdx.z * gridDim.x + blockIdx.x) * 128;
    const int nBase = blockIdx.y * 128;

    if (tid < 128)
        srcRow[tid] = GATHER ? (g_perm[mBase + tid] >> 1) : (mBase + tid);
    __syncthreads();

    const float* B = Bg + (size_t)blockIdx.z * (1024u * 1024u);

    // per-thread cp.async endpoints (constant across K chunks)
    const float* aSrc[4]; uint32_t aDst[4];
    const float* bSrc[4]; uint32_t bDst[4];
    #pragma unroll
    for (int it = 0; it < 4; ++it) {
        const int ia = tid + it * 256;
        const int r = ia >> 3, q = ia & 7;                  // A: 128 rows x 8 f4
        aSrc[it] = A + (size_t)srcRow[r] * 1024 + q * 4;
        aDst[it] = smem + r * (A_STRIDE * 4) + q * 16;
        const int kk = ia >> 5, n4 = ia & 31;               // B: 32 rows x 32 f4
        bSrc[it] = B + (size_t)kk * 1024 + nBase + n4 * 4;
        bDst[it] = smem + 18432 + kk * (B_STRIDE * 4) + n4 * 16;
    }

    float d[2][8][4];
    #pragma unroll
    for (int f = 0; f < 2; ++f)
        #pragma unroll
        for (int g = 0; g < 8; ++g)
            #pragma unroll
            for (int j = 0; j < 4; ++j) d[f][g][j] = 0.f;

    // --- issue stage kt into buffer kt&1 -------------------------------------
    #define ISSUE(kt) do {                                                   \
        const uint32_t off_ = ((kt) & 1) * STG_BYTES;                        \
        const int k0_ = (kt) * 32;                                           \
        _Pragma("unroll")                                                    \
        for (int it = 0; it < 4; ++it)                                       \
            cp_async16(aDst[it] + off_, aSrc[it] + k0_);                     \
        _Pragma("unroll")                                                    \
        for (int it = 0; it < 4; ++it)                                       \
            cp_async16(bDst[it] + off_, bSrc[it] + (size_t)k0_ * 1024);      \
        cp_commit();                                                         \
    } while (0)

    ISSUE(0);

    for (int kt = 0; kt < 32; ++kt) {
        if (kt + 1 < 32) { ISSUE(kt + 1); cp_wait<1>(); }
        else             { cp_wait<0>(); }
        __syncthreads();

        const float* As = (const float*)(sm + (kt & 1) * STG_BYTES);
        const float* Bs = (const float*)(sm + (kt & 1) * STG_BYTES + 18432);

        #pragma unroll
        for (int kk = 0; kk < 4; ++kk) {
            const int k = kk * 8;
            uint32_t af[2][4];
            #pragma unroll
            for (int f = 0; f < 2; ++f) {
                const int r = wm * 32 + f * 16 + row4;
                af[f][0] = f2tf32(As[r * A_STRIDE + k + kq]);
                af[f][1] = f2tf32(As[(r + 8) * A_STRIDE + k + kq]);
                af[f][2] = f2tf32(As[r * A_STRIDE + k + kq + 4]);
                af[f][3] = f2tf32(As[(r + 8) * A_STRIDE + k + kq + 4]);
            }
            uint32_t bf[8][2];
            #pragma unroll
            for (int g = 0; g < 8; ++g) {
                const int c = wn * 64 + g * 8 + row4;
                bf[g][0] = f2tf32(Bs[(k + kq) * B_STRIDE + c]);
                bf[g][1] = f2tf32(Bs[(k + kq + 4) * B_STRIDE + c]);
            }
            #pragma unroll
            for (int f = 0; f < 2; ++f)
                #pragma unroll
                for (int g = 0; g < 8; ++g)
                    mma_tf32(d[f][g], af[f], bf[g]);
        }
        __syncthreads();
    }

    // --- epilogue -------------------------------------------------------------
    #pragma unroll
    for (int f = 0; f < 2; ++f) {
        const int r0 = mBase + wm * 32 + f * 16 + row4;
        #pragma unroll
        for (int g = 0; g < 8; ++g) {
            const int c = nBase + wn * 64 + g * 8 + kq * 2;
            float2 v0 = make_float2(d[f][g][0], d[f][g][1]);
            float2 v1 = make_float2(d[f][g][2], d[f][g][3]);
            if (EPI == 1) {
                const float2 u0 = *(const float2*)(Aux + (size_t)r0 * 1024 + c);
                const float2 u1 = *(const float2*)(Aux + (size_t)(r0 + 8) * 1024 + c);
                v0.x = silu(v0.x) * u0.x;  v0.y = silu(v0.y) * u0.y;
                v1.x = silu(v1.x) * u1.x;  v1.y = silu(v1.y) * u1.y;
            }
            *(float2*)(Out + (size_t)r0 * 1024 + c) = v0;
            *(float2*)(Out + (size_t)(r0 + 8) * 1024 + c) = v1;
        }
    }
}

// =============================================================================
// Final combine: out[t] = w0*Y[inv[2t]] + w1*Y[inv[2t+1]] + sigmoid(x.gw)*S[t]
// =============================================================================
__global__ void __launch_bounds__(256) combine_kernel(
    const float* __restrict__ X, const float* __restrict__ tw,
    const float* __restrict__ gw, float* __restrict__ out)
{
    const int t = blockIdx.x;
    const int tid = threadIdx.x;
    __shared__ float red[256];
    const float* xr = X + (size_t)t * 1024;
    float acc = 0.f;
    #pragma unroll
    for (int it = 0; it < 4; ++it) {
        const int dd = tid + it * 256;
        acc += xr[dd] * gw[dd];
    }
    red[tid] = acc;
    __syncthreads();
    for (int s = 128; s > 0; s >>= 1) {
        if (tid < s) red[tid] += red[tid + s];
        __syncthreads();
    }
    const float g = 1.f / (1.f + __expf(-red[0]));
    const int r0 = g_inv[2 * t], r1 = g_inv[2 * t + 1];
    const float w0 = tw[2 * t], w1 = tw[2 * t + 1];
    const float4 a = ((const float4*)(g_Y + (size_t)r0 * 1024))[tid];
    const float4 b = ((const float4*)(g_Y + (size_t)r1 * 1024))[tid];
    const float4 c = ((const float4*)(g_S + (size_t)t  * 1024))[tid];
    float4 r;
    r.x = w0 * a.x + w1 * b.x + g * c.x;
    r.y = w0 * a.y + w1 * b.y + g * c.y;
    r.z = w0 * a.z + w1 * b.z + g * c.z;
    r.w = w0 * a.w + w1 * b.w + g * c.w;
    ((float4*)(out + (size_t)t * 1024))[tid] = r;
}

// =============================================================================
extern "C" void kernel_launch(void* const* d_in, const int* in_sizes, int n_in,
                              void* d_out, int out_size) {
    (void)in_sizes; (void)n_in; (void)out_size;
    const float* X   = (const float*)d_in[0];
    const float* tw  = (const float*)d_in[1];
    const float* wg  = (const float*)d_in[2];
    const float* wu  = (const float*)d_in[3];
    const float* wd  = (const float*)d_in[4];
    const float* swg = (const float*)d_in[5];
    const float* swu = (const float*)d_in[6];
    const float* swd = (const float*)d_in[7];
    const float* gw  = (const float*)d_in[8];
    const int*   tki = (const int*)d_in[9];
    float* out = (float*)d_out;

    float *H = nullptr, *Y = nullptr, *SH = nullptr, *S = nullptr;
    cudaGetSymbolAddress((void**)&H,  g_H);
    cudaGetSymbolAddress((void**)&Y,  g_Y);
    cudaGetSymbolAddress((void**)&SH, g_SH);
    cudaGetSymbolAddress((void**)&S,  g_S);

    const int dynSmem = 2 * STG_BYTES + 512;   // 71168
    cudaFuncSetAttribute(gemm_mma<true,  0>, cudaFuncAttributeMaxDynamicSharedMemorySize, dynSmem);
    cudaFuncSetAttribute(gemm_mma<true,  1>, cudaFuncAttributeMaxDynamicSharedMemorySize, dynSmem);
    cudaFuncSetAttribute(gemm_mma<false, 0>, cudaFuncAttributeMaxDynamicSharedMemorySize, dynSmem);
    cudaFuncSetAttribute(gemm_mma<false, 1>, cudaFuncAttributeMaxDynamicSharedMemorySize, dynSmem);

    // 1. dispatch permutation
    build_perm_kernel<<<NEXP, 256>>>(tki);
    // 2. routed up:   U = Xperm @ Wu            -> g_H
    gemm_mma<true,  0><<<dim3(8, 8, NEXP), 256, dynSmem>>>(X, wu, nullptr, H);
    // 3. routed gate: H = silu(Xperm @ Wg) * U  -> g_H (in place)
    gemm_mma<true,  1><<<dim3(8, 8, NEXP), 256, dynSmem>>>(X, wg, H, H);
    // 4. routed down: Y = H @ Wd                -> g_Y
    gemm_mma<false, 0><<<dim3(8, 8, NEXP), 256, dynSmem>>>(H, wd, nullptr, Y);
    // 5. shared up:   SU = X @ swu              -> g_SH
    gemm_mma<false, 0><<<dim3(32, 8, 1), 256, dynSmem>>>(X, swu, nullptr, SH);
    // 6. shared gate: SH = silu(X @ swg) * SU   -> g_SH (in place)
    gemm_mma<false, 1><<<dim3(32, 8, 1), 256, dynSmem>>>(X, swg, SH, SH);
    // 7. shared down: S = SH @ swd              -> g_S
    gemm_mma<false, 0><<<dim3(32, 8, 1), 256, dynSmem>>>(SH, swd, nullptr, S);
    // 8. combine
    combine_kernel<<<NTOK, 256>>>(X, tw, gw, out);
}

// round 3
// speedup vs baseline: 1.0642x; 1.0642x over previous
#include <cuda_runtime.h>
#include <cuda_bf16.h>
#include <cstdint>

// =============================================================================
// MoE fused layer, plain sm_103 target (tcgen05 unavailable -> legacy mma.sync
// tf32 m16n8k8). R3: tf32 pre-rounding pass removes all in-loop CVTs; warp tile
// 64x64 (CTA 128x256, 8 warps, 3-stage cp.async) for LDS:MMA = 1.0.
// T=4096, D=1024, E=8, K=2, F=SF=1024.
// =============================================================================

#define NEXP   8
#define NTOK   4096
#define NROWS  8192
#define CPE    1024

// ---------------- scratch (device globals: allocation-free rule) ------------
__device__ float g_H [8192u * 1024u];   // routed: U then H=silu(G)*U (in place)
__device__ float g_Y [8192u * 1024u];   // routed down output (permuted order)
__device__ float g_SH[4096u * 1024u];   // shared: SU then SH=silu(SG)*SU
__device__ float g_S [4096u * 1024u];   // shared down output
__device__ int   g_perm[8192];
__device__ int   g_inv [8192];
// tf32-pre-rounded copies of all MMA inputs
__device__ float g_X  [4096u * 1024u];
__device__ float g_wg [8u * 1024u * 1024u];
__device__ float g_wu [8u * 1024u * 1024u];
__device__ float g_wd [8u * 1024u * 1024u];
__device__ float g_swg[1024u * 1024u];
__device__ float g_swu[1024u * 1024u];
__device__ float g_swd[1024u * 1024u];

// ---------------- helpers ----------------------------------------------------
__device__ __forceinline__ uint32_t smem_u32(const void* p) {
    uint32_t a;
    asm("{ .reg .u64 t; cvta.to.shared.u64 t, %1; cvt.u32.u64 %0, t; }"
        : "=r"(a) : "l"(p));
    return a;
}

__device__ __forceinline__ void cp_async16(uint32_t dst, const void* src) {
    asm volatile("cp.async.cg.shared.global [%0], [%1], 16;"
                 :: "r"(dst), "l"(src) : "memory");
}
__device__ __forceinline__ void cp_commit() {
    asm volatile("cp.async.commit_group;" ::: "memory");
}
template<int N>
__device__ __forceinline__ void cp_wait() {
    asm volatile("cp.async.wait_group %0;" :: "n"(N) : "memory");
}

__device__ __forceinline__ uint32_t f2tf32(float f) {
    uint32_t r;
    asm("cvt.rna.tf32.f32 %0, %1;" : "=r"(r) : "f"(f));
    return r;
}
__device__ __forceinline__ float rnd_tf32(float f) {
    return __uint_as_float(f2tf32(f));
}

__device__ __forceinline__ void mma_tf32(float* d, const uint32_t* a,
                                         const uint32_t* b) {
    asm volatile(
        "mma.sync.aligned.m16n8k8.row.col.f32.tf32.tf32.f32 "
        "{%0,%1,%2,%3}, {%4,%5,%6,%7}, {%8,%9}, {%0,%1,%2,%3};"
        : "+f"(d[0]), "+f"(d[1]), "+f"(d[2]), "+f"(d[3])
        : "r"(a[0]), "r"(a[1]), "r"(a[2]), "r"(a[3]), "r"(b[0]), "r"(b[1]));
}

__device__ __forceinline__ float silu(float x) {
    return x / (1.f + __expf(-x));
}

// =============================================================================
// Fused tf32 pre-rounding pass over X and all weight tensors.
// Segments (float4 units): X 1048576 | wg 2097152 | wu | wd | swg 262144 | swu | swd
// =============================================================================
__device__ __forceinline__ float4 cvt4(const float4 v) {
    float4 r;
    r.x = rnd_tf32(v.x); r.y = rnd_tf32(v.y);
    r.z = rnd_tf32(v.z); r.w = rnd_tf32(v.w);
    return r;
}

__global__ void __launch_bounds__(256) cvt_all(
    const float* __restrict__ x,
    const float* __restrict__ wg,  const float* __restrict__ wu,
    const float* __restrict__ wd,
    const float* __restrict__ swg, const float* __restrict__ swu,
    const float* __restrict__ swd)
{
    const size_t total = 8126464u;   // 1M + 3*2M + 3*256K (float4)
    for (size_t i = (size_t)blockIdx.x * blockDim.x + threadIdx.x;
         i < total; i += (size_t)gridDim.x * blockDim.x) {
        const float4* s; float4* d; size_t j;
        if      (i < 1048576u) { s = (const float4*)x;   d = (float4*)g_X;   j = i; }
        else if (i < 3145728u) { s = (const float4*)wg;  d = (float4*)g_wg;  j = i - 1048576u; }
        else if (i < 5242880u) { s = (const float4*)wu;  d = (float4*)g_wu;  j = i - 3145728u; }
        else if (i < 7340032u) { s = (const float4*)wd;  d = (float4*)g_wd;  j = i - 5242880u; }
        else if (i < 7602176u) { s = (const float4*)swg; d = (float4*)g_swg; j = i - 7340032u; }
        else if (i < 7864320u) { s = (const float4*)swu; d = (float4*)g_swu; j = i - 7602176u; }
        else                   { s = (const float4*)swd; d = (float4*)g_swd; j = i - 7864320u; }
        d[j] = cvt4(s[j]);
    }
}

// =============================================================================
// Stable counting-sort permutation (matches jnp.argsort stability).
// =============================================================================
__global__ void build_perm_kernel(const int* __restrict__ tki) {
    const int e = blockIdx.x;
    const int tid = threadIdx.x;
    __shared__ int scan[256];
    __shared__ int basev;
    if (tid == 0) basev = 0;
    __syncthreads();
    for (int start = 0; start < NROWS; start += 256) {
        const int i = start + tid;
        const int m = (tki[i] == e) ? 1 : 0;
        scan[tid] = m;
        __syncthreads();
        #pragma unroll
        for (int off = 1; off < 256; off <<= 1) {
            int v = (tid >= off) ? scan[tid - off] : 0;
            __syncthreads();
            scan[tid] += v;
            __syncthreads();
        }
        if (m) {
            const int dest = e * CPE + basev + scan[tid] - 1;
            g_perm[dest] = i;
            g_inv[i] = dest;
        }
        __syncthreads();
        if (tid == 0) basev += scan[255];
        __syncthreads();
    }
}

// =============================================================================
// tf32 mma.sync GEMM: CTA 128x256, K in 32-chunks, 8 warps (2m x 4n grid),
// warp tile 64x64 (4 m-frags x 8 n-frags m16n8k8), 3-stage cp.async pipeline.
// All MMA inputs must be tf32-exact fp32 (pre-rounded) -> no in-loop CVTs.
//   EPI 0: Out = D.   EPI 1: Out = round_tf32(silu(D) * Aux)  (Aux may alias).
// smem/stage: A 128x36 f32 (18432 B) + B 32x264 f32 (33792 B) = 52224 B.
// =============================================================================
#define STG_BYTES 52224
#define A_STRIDE  36
#define B_STRIDE  264
#define DSMEM     (3 * STG_BYTES + 512)

template<bool GATHER, int EPI>
__global__ void __launch_bounds__(256, 1) gemm_mma(
    const float* __restrict__ A,
    const float* __restrict__ Bg,
    const float* __restrict__ Aux,
    float* __restrict__ Out)
{
    extern __shared__ char sm[];
    const uint32_t smem = smem_u32(sm);
    int* srcRow = (int*)(sm + 3 * STG_BYTES);

    const int tid  = threadIdx.x;
    const int wid  = tid >> 5;
    const int lane = tid & 31;
    const int wm   = wid & 1;          // warp m (0..1)  -> m offset wm*64
    const int wn   = wid >> 1;         // warp n (0..3)  -> n offset wn*64
    const int row4 = lane >> 2;        // groupID
    const int kq   = lane & 3;         // threadID-in-group

    const int mBase = (blockIdx.z * gridDim.x + blockIdx.x) * 128;
    const int nBase = blockIdx.y * 256;

    if (tid < 128)
        srcRow[tid] = GATHER ? (g_perm[mBase + tid] >> 1) : (mBase + tid);
    __syncthreads();

    const float* B = Bg + (size_t)blockIdx.z * (1024u * 1024u);

    // cp.async endpoints (per stage: A 1024 f4, B 2048 f4; 256 threads)
    const float* aSrc[4]; uint32_t aDst[4];
    #pragma unroll
    for (int it = 0; it < 4; ++it) {
        const int i = tid + it * 256;
        const int r = i >> 3, q = i & 7;        // 128 rows x 8 float4
        aSrc[it] = A + (size_t)srcRow[r] * 1024 + q * 4;
        aDst[it] = smem + r * (A_STRIDE * 4) + q * 16;
    }
    const float* bSrc[8]; uint32_t bDst[8];
    #pragma unroll
    for (int it = 0; it < 8; ++it) {
        const int i = tid + it * 256;
        const int kk = i >> 6, n4 = i & 63;     // 32 k-rows x 64 float4
        bSrc[it] = B + (size_t)kk * 1024 + nBase + n4 * 4;
        bDst[it] = smem + 18432 + kk * (B_STRIDE * 4) + n4 * 16;
    }

    float d[4][8][4];
    #pragma unroll
    for (int f = 0; f < 4; ++f)
        #pragma unroll
        for (int g = 0; g < 8; ++g)
            #pragma unroll
            for (int j = 0; j < 4; ++j) d[f][g][j] = 0.f;

    auto issue = [&](int kt, uint32_t soff) {
        const int k0 = kt * 32;
        #pragma unroll
        for (int it = 0; it < 4; ++it)
            cp_async16(aDst[it] + soff, aSrc[it] + k0);
        #pragma unroll
        for (int it = 0; it < 8; ++it)
            cp_async16(bDst[it] + soff, bSrc[it] + (size_t)k0 * 1024);
        cp_commit();
    };

    issue(0, 0);
    issue(1, STG_BYTES);

    uint32_t csOff = 0;                 // compute-stage byte offset
    uint32_t nsOff = 2 * STG_BYTES;     // next-fill-stage byte offset

    for (int kt = 0; kt < 32; ++kt) {
        if (kt < 30) {
            issue(kt + 2, nsOff);
            nsOff = (nsOff == 2 * STG_BYTES) ? 0 : nsOff + STG_BYTES;
            cp_wait<2>();
        } else if (kt == 30) cp_wait<1>();
        else                 cp_wait<0>();
        __syncthreads();

        const uint32_t* As = (const uint32_t*)(sm + csOff);
        const uint32_t* Bs = (const uint32_t*)(sm + csOff + 18432);

        #pragma unroll
        for (int kk = 0; kk < 4; ++kk) {
            const int k = kk * 8;
            uint32_t af[4][4];
            #pragma unroll
            for (int f = 0; f < 4; ++f) {
                const int r = wm * 64 + f * 16 + row4;
                af[f][0] = As[r * A_STRIDE + k + kq];
                af[f][1] = As[(r + 8) * A_STRIDE + k + kq];
                af[f][2] = As[r * A_STRIDE + k + kq + 4];
                af[f][3] = As[(r + 8) * A_STRIDE + k + kq + 4];
            }
            uint32_t bf[8][2];
            #pragma unroll
            for (int g = 0; g < 8; ++g) {
                const int c = wn * 64 + g * 8 + row4;
                bf[g][0] = Bs[(k + kq) * B_STRIDE + c];
                bf[g][1] = Bs[(k + kq + 4) * B_STRIDE + c];
            }
            #pragma unroll
            for (int f = 0; f < 4; ++f)
                #pragma unroll
                for (int g = 0; g < 8; ++g)
                    mma_tf32(d[f][g], af[f], bf[g]);
        }
        __syncthreads();
        csOff = (csOff == 2 * STG_BYTES) ? 0 : csOff + STG_BYTES;
    }

    // --- epilogue -------------------------------------------------------------
    #pragma unroll
    for (int f = 0; f < 4; ++f) {
        const int r0 = mBase + wm * 64 + f * 16 + row4;
        #pragma unroll
        for (int g = 0; g < 8; ++g) {
            const int c = nBase + wn * 64 + g * 8 + kq * 2;
            float2 v0 = make_float2(d[f][g][0], d[f][g][1]);
            float2 v1 = make_float2(d[f][g][2], d[f][g][3]);
            if (EPI == 1) {
                const float2 u0 = *(const float2*)(Aux + (size_t)r0 * 1024 + c);
                const float2 u1 = *(const float2*)(Aux + (size_t)(r0 + 8) * 1024 + c);
                v0.x = rnd_tf32(silu(v0.x) * u0.x);
                v0.y = rnd_tf32(silu(v0.y) * u0.y);
                v1.x = rnd_tf32(silu(v1.x) * u1.x);
                v1.y = rnd_tf32(silu(v1.y) * u1.y);
            }
            *(float2*)(Out + (size_t)r0 * 1024 + c) = v0;
            *(float2*)(Out + (size_t)(r0 + 8) * 1024 + c) = v1;
        }
    }
}

// =============================================================================
// Final combine: out[t] = w0*Y[inv[2t]] + w1*Y[inv[2t+1]] + sigmoid(x.gw)*S[t]
// =============================================================================
__global__ void __launch_bounds__(256) combine_kernel(
    const float* __restrict__ X, const float* __restrict__ tw,
    const float* __restrict__ gw, float* __restrict__ out)
{
    const int t = blockIdx.x;
    const int tid = threadIdx.x;
    __shared__ float red[256];
    const float* xr = X + (size_t)t * 1024;
    float acc = 0.f;
    #pragma unroll
    for (int it = 0; it < 4; ++it) {
        const int dd = tid + it * 256;
        acc += xr[dd] * gw[dd];
    }
    red[tid] = acc;
    __syncthreads();
    for (int s = 128; s > 0; s >>= 1) {
        if (tid < s) red[tid] += red[tid + s];
        __syncthreads();
    }
    const float g = 1.f / (1.f + __expf(-red[0]));
    const int r0 = g_inv[2 * t], r1 = g_inv[2 * t + 1];
    const float w0 = tw[2 * t], w1 = tw[2 * t + 1];
    const float4 a = ((const float4*)(g_Y + (size_t)r0 * 1024))[tid];
    const float4 b = ((const float4*)(g_Y + (size_t)r1 * 1024))[tid];
    const float4 c = ((const float4*)(g_S + (size_t)t  * 1024))[tid];
    float4 r;
    r.x = w0 * a.x + w1 * b.x + g * c.x;
    r.y = w0 * a.y + w1 * b.y + g * c.y;
    r.z = w0 * a.z + w1 * b.z + g * c.z;
    r.w = w0 * a.w + w1 * b.w + g * c.w;
    ((float4*)(out + (size_t)t * 1024))[tid] = r;
}

// =============================================================================
extern "C" void kernel_launch(void* const* d_in, const int* in_sizes, int n_in,
                              void* d_out, int out_size) {
    (void)in_sizes; (void)n_in; (void)out_size;
    const float* X   = (const float*)d_in[0];
    const float* tw  = (const float*)d_in[1];
    const float* wg  = (const float*)d_in[2];
    const float* wu  = (const float*)d_in[3];
    const float* wd  = (const float*)d_in[4];
    const float* swg = (const float*)d_in[5];
    const float* swu = (const float*)d_in[6];
    const float* swd = (const float*)d_in[7];
    const float* gw  = (const float*)d_in[8];
    const int*   tki = (const int*)d_in[9];
    float* out = (float*)d_out;

    float *H, *Y, *SH, *S, *Xr, *Wg, *Wu, *Wd, *Sg, *Su, *Sd;
    cudaGetSymbolAddress((void**)&H,  g_H);
    cudaGetSymbolAddress((void**)&Y,  g_Y);
    cudaGetSymbolAddress((void**)&SH, g_SH);
    cudaGetSymbolAddress((void**)&S,  g_S);
    cudaGetSymbolAddress((void**)&Xr, g_X);
    cudaGetSymbolAddress((void**)&Wg, g_wg);
    cudaGetSymbolAddress((void**)&Wu, g_wu);
    cudaGetSymbolAddress((void**)&Wd, g_wd);
    cudaGetSymbolAddress((void**)&Sg, g_swg);
    cudaGetSymbolAddress((void**)&Su, g_swu);
    cudaGetSymbolAddress((void**)&Sd, g_swd);

    cudaFuncSetAttribute(gemm_mma<true,  0>, cudaFuncAttributeMaxDynamicSharedMemorySize, DSMEM);
    cudaFuncSetAttribute(gemm_mma<true,  1>, cudaFuncAttributeMaxDynamicSharedMemorySize, DSMEM);
    cudaFuncSetAttribute(gemm_mma<false, 0>, cudaFuncAttributeMaxDynamicSharedMemorySize, DSMEM);
    cudaFuncSetAttribute(gemm_mma<false, 1>, cudaFuncAttributeMaxDynamicSharedMemorySize, DSMEM);

    // 0. tf32 pre-rounding of all MMA inputs + dispatch permutation
    cvt_all<<<1184, 256>>>(X, wg, wu, wd, swg, swu, swd);
    build_perm_kernel<<<NEXP, 256>>>(tki);
    // 1. routed up:   U = Xperm @ Wu             -> g_H
    gemm_mma<true,  0><<<dim3(8, 4, NEXP), 256, DSMEM>>>(Xr, Wu, nullptr, H);
    // 2. routed gate: H = rnd(silu(Xperm@Wg)*U)  -> g_H (in place)
    gemm_mma<true,  1><<<dim3(8, 4, NEXP), 256, DSMEM>>>(Xr, Wg, H, H);
    // 3. routed down: Y = H @ Wd                 -> g_Y
    gemm_mma<false, 0><<<dim3(8, 4, NEXP), 256, DSMEM>>>(H, Wd, nullptr, Y);
    // 4. shared up:   SU = X @ swu               -> g_SH
    gemm_mma<false, 0><<<dim3(32, 4, 1), 256, DSMEM>>>(Xr, Su, nullptr, SH);
    // 5. shared gate: SH = rnd(silu(X@swg)*SU)   -> g_SH (in place)
    gemm_mma<false, 1><<<dim3(32, 4, 1), 256, DSMEM>>>(Xr, Sg, SH, SH);
    // 6. shared down: S = SH @ swd               -> g_S
    gemm_mma<false, 0><<<dim3(32, 4, 1), 256, DSMEM>>>(SH, Sd, nullptr, S);
    // 7. combine
    combine_kernel<<<NTOK, 256>>>(X, tw, gw, out);
}

// round 4
// speedup vs baseline: 1.3382x; 1.2574x over previous
#include <cuda_runtime.h>
#include <cuda_bf16.h>
#include <cstdint>

// =============================================================================
// MoE fused layer, plain sm_103 target (tcgen05 not exposed by toolchain ->
// legacy mma.sync tf32 m16n8k8). R4: ldmatrix.x4 A-fragments, warp tile 64x32,
// 2 CTA/SM, fused gate+up kernel with smem exchange, 1 sync per K-chunk.
// T=4096, D=1024, E=8, K=2, F=SF=1024.
// =============================================================================

#define NEXP   8
#define NTOK   4096
#define NROWS  8192
#define CPE    1024

// ---------------- scratch (device globals: allocation-free rule) ------------
__device__ float g_H [8192u * 1024u];   // routed hidden = silu(G)*U (tf32-exact)
__device__ float g_Y [8192u * 1024u];   // routed down out (permuted order)
__device__ float g_SH[4096u * 1024u];   // shared hidden
__device__ float g_S [4096u * 1024u];   // shared down out
__device__ int   g_perm[8192];
__device__ int   g_inv [8192];
// tf32-pre-rounded MMA inputs
__device__ float g_X  [4096u * 1024u];
__device__ float g_wg [8u * 1024u * 1024u];
__device__ float g_wu [8u * 1024u * 1024u];
__device__ float g_wd [8u * 1024u * 1024u];
__device__ float g_swg[1024u * 1024u];
__device__ float g_swu[1024u * 1024u];
__device__ float g_swd[1024u * 1024u];

// ---------------- helpers ----------------------------------------------------
__device__ __forceinline__ uint32_t smem_u32(const void* p) {
    uint32_t a;
    asm("{ .reg .u64 t; cvta.to.shared.u64 t, %1; cvt.u32.u64 %0, t; }"
        : "=r"(a) : "l"(p));
    return a;
}
__device__ __forceinline__ void cp_async16(uint32_t dst, const void* src) {
    asm volatile("cp.async.cg.shared.global [%0], [%1], 16;"
                 :: "r"(dst), "l"(src) : "memory");
}
__device__ __forceinline__ void cp_commit() {
    asm volatile("cp.async.commit_group;" ::: "memory");
}
template<int N>
__device__ __forceinline__ void cp_wait() {
    asm volatile("cp.async.wait_group %0;" :: "n"(N) : "memory");
}
__device__ __forceinline__ uint32_t f2tf32(float f) {
    uint32_t r;
    asm("cvt.rna.tf32.f32 %0, %1;" : "=r"(r) : "f"(f));
    return r;
}
__device__ __forceinline__ float rnd_tf32(float f) {
    return __uint_as_float(f2tf32(f));
}
__device__ __forceinline__ void ldsm_x4(uint32_t* r, uint32_t addr) {
    asm volatile("ldmatrix.sync.aligned.m8n8.x4.shared.b16 {%0,%1,%2,%3}, [%4];"
                 : "=r"(r[0]), "=r"(r[1]), "=r"(r[2]), "=r"(r[3]) : "r"(addr));
}
__device__ __forceinline__ void mma_tf32(float* d, const uint32_t* a,
                                         const uint32_t* b) {
    asm volatile(
        "mma.sync.aligned.m16n8k8.row.col.f32.tf32.tf32.f32 "
        "{%0,%1,%2,%3}, {%4,%5,%6,%7}, {%8,%9}, {%0,%1,%2,%3};"
        : "+f"(d[0]), "+f"(d[1]), "+f"(d[2]), "+f"(d[3])
        : "r"(a[0]), "r"(a[1]), "r"(a[2]), "r"(a[3]), "r"(b[0]), "r"(b[1]));
}
__device__ __forceinline__ float silu(float x) {
    return x / (1.f + __expf(-x));
}

// =============================================================================
// tf32 pre-rounding of all MMA inputs (weights + X).
// =============================================================================
__device__ __forceinline__ float4 cvt4(const float4 v) {
    float4 r;
    r.x = rnd_tf32(v.x); r.y = rnd_tf32(v.y);
    r.z = rnd_tf32(v.z); r.w = rnd_tf32(v.w);
    return r;
}
__global__ void __launch_bounds__(256) cvt_all(
    const float* __restrict__ x,
    const float* __restrict__ wg,  const float* __restrict__ wu,
    const float* __restrict__ wd,
    const float* __restrict__ swg, const float* __restrict__ swu,
    const float* __restrict__ swd)
{
    const size_t total = 8126464u;   // float4 units
    for (size_t i = (size_t)blockIdx.x * blockDim.x + threadIdx.x;
         i < total; i += (size_t)gridDim.x * blockDim.x) {
        const float4* s; float4* d; size_t j;
        if      (i < 1048576u) { s = (const float4*)x;   d = (float4*)g_X;   j = i; }
        else if (i < 3145728u) { s = (const float4*)wg;  d = (float4*)g_wg;  j = i - 1048576u; }
        else if (i < 5242880u) { s = (const float4*)wu;  d = (float4*)g_wu;  j = i - 3145728u; }
        else if (i < 7340032u) { s = (const float4*)wd;  d = (float4*)g_wd;  j = i - 5242880u; }
        else if (i < 7602176u) { s = (const float4*)swg; d = (float4*)g_swg; j = i - 7340032u; }
        else if (i < 7864320u) { s = (const float4*)swu; d = (float4*)g_swu; j = i - 7602176u; }
        else                   { s = (const float4*)swd; d = (float4*)g_swd; j = i - 7864320u; }
        d[j] = cvt4(s[j]);
    }
}

// =============================================================================
// Stable counting-sort permutation (matches jnp.argsort stability).
// =============================================================================
__global__ void build_perm_kernel(const int* __restrict__ tki) {
    const int e = blockIdx.x;
    const int tid = threadIdx.x;
    __shared__ int scan[256];
    __shared__ int basev;
    if (tid == 0) basev = 0;
    __syncthreads();
    for (int start = 0; start < NROWS; start += 256) {
        const int i = start + tid;
        const int m = (tki[i] == e) ? 1 : 0;
        scan[tid] = m;
        __syncthreads();
        #pragma unroll
        for (int off = 1; off < 256; off <<= 1) {
            int v = (tid >= off) ? scan[tid - off] : 0;
            __syncthreads();
            scan[tid] += v;
            __syncthreads();
        }
        if (m) {
            const int dest = e * CPE + basev + scan[tid] - 1;
            g_perm[dest] = i;
            g_inv[i] = dest;
        }
        __syncthreads();
        if (tid == 0) basev += scan[255];
        __syncthreads();
    }
}

// =============================================================================
// Fused gate+up GEMM. CTA: 128 m-rows x 64 n-cols, BOTH matrices.
// Warps 0-3: gate, 4-7: up. Warp tile 64x32 (4 m-frags x 4 n-frags).
// Epilogue: up warps stage U in smem; gate warps emit rnd(silu(G)*U).
// smem/stage: A 128x36 f32 (18432) + 2x B 32x72 f32 (18432) = 36864. 3 stages.
// =============================================================================
#define GU_AS    36
#define GU_BS    72
#define GU_AB    18432
#define GU_STG   36864
#define GU_SMEM  (3 * GU_STG + 512)

template<bool GATHER>
__global__ void __launch_bounds__(256, 2) gemm_gu(
    const float* __restrict__ A,
    const float* __restrict__ B0g,
    const float* __restrict__ B1g,
    float* __restrict__ Out)
{
    extern __shared__ char sm[];
    const uint32_t smem = smem_u32(sm);
    int* srcRow = (int*)(sm + 3 * GU_STG);

    const int tid  = threadIdx.x;
    const int wid  = tid >> 5;
    const int lane = tid & 31;
    const int row4 = lane >> 2;
    const int kq   = lane & 3;
    const int mat  = wid >> 2;           // 0 = gate, 1 = up
    const int wq   = wid & 3;
    const int R    = (wq >> 1) * 64;     // warp m-base
    const int nOff = (wq & 1) * 32;      // warp n-base

    const int mBase = (blockIdx.z * gridDim.x + blockIdx.x) * 128;
    const int nBase = blockIdx.y * 64;

    if (tid < 128)
        srcRow[tid] = GATHER ? (g_perm[mBase + tid] >> 1) : (mBase + tid);
    __syncthreads();

    const float* B0 = B0g + (size_t)blockIdx.z * (1024u * 1024u);
    const float* B1 = B1g + (size_t)blockIdx.z * (1024u * 1024u);

    // cp.async endpoints: per stage A 1024 f4, B 1024 f4; 256 threads, 4 each.
    const float* aSrc[4]; uint32_t aDst[4];
    const float* bSrc[4]; uint32_t bDst[4];
    #pragma unroll
    for (int it = 0; it < 4; ++it) {
        const int ia = tid + it * 256;
        const int r = ia >> 3, q = ia & 7;               // A: 128 rows x 8 f4
        aSrc[it] = A + (size_t)srcRow[r] * 1024 + q * 4;
        aDst[it] = smem + r * (GU_AS * 4) + q * 16;
        const int mm = ia >> 9, kk = (ia >> 4) & 31, n4 = ia & 15;
        bSrc[it] = (mm ? B1 : B0) + (size_t)kk * 1024 + nBase + n4 * 4;
        bDst[it] = smem + GU_AB + mm * 9216 + kk * (GU_BS * 4) + n4 * 16;
    }

    // ldmatrix per-thread base: threads 0-7->m0, 8-15->m1, 16-23->m2, 24-31->m3
    const int lr = lane & 7, hi8 = (lane >> 3) & 1, kHalf = lane >> 4;
    const uint32_t aLdBase =
        smem + ((R + hi8 * 8 + lr) * GU_AS + kHalf * 4) * 4;

    float d[4][4][4];
    #pragma unroll
    for (int f = 0; f < 4; ++f)
        #pragma unroll
        for (int g = 0; g < 4; ++g)
            #pragma unroll
            for (int j = 0; j < 4; ++j) d[f][g][j] = 0.f;

    auto issue = [&](int kt, uint32_t soff) {
        const int k0 = kt * 32;
        #pragma unroll
        for (int it = 0; it < 4; ++it)
            cp_async16(aDst[it] + soff, aSrc[it] + k0);
        #pragma unroll
        for (int it = 0; it < 4; ++it)
            cp_async16(bDst[it] + soff, bSrc[it] + (size_t)k0 * 1024);
        cp_commit();
    };

    issue(0, 0);
    issue(1, GU_STG);

    uint32_t cs = 0, ns = 2 * GU_STG;
    for (int kt = 0; kt < 32; ++kt) {
        if (kt < 31) cp_wait<1>(); else cp_wait<0>();
        __syncthreads();
        if (kt < 30) {
            issue(kt + 2, ns);
            ns = (ns == 2 * GU_STG) ? 0 : ns + GU_STG;
        }
        const uint32_t* Bs =
            (const uint32_t*)(sm + cs + GU_AB + mat * 9216);
        const uint32_t aOff = aLdBase + cs;

        #pragma unroll
        for (int kk = 0; kk < 4; ++kk) {
            const int k = kk * 8;
            uint32_t af[4][4];
            #pragma unroll
            for (int f = 0; f < 4; ++f)
                ldsm_x4(af[f], aOff + f * (16 * GU_AS * 4) + kk * 32);
            uint32_t bf[4][2];
            #pragma unroll
            for (int g = 0; g < 4; ++g) {
                const int c = nOff + g * 8 + row4;
                bf[g][0] = Bs[(k + kq) * GU_BS + c];
                bf[g][1] = Bs[(k + kq + 4) * GU_BS + c];
            }
            #pragma unroll
            for (int f = 0; f < 4; ++f)
                #pragma unroll
                for (int g = 0; g < 4; ++g)
                    mma_tf32(d[f][g], af[f], bf[g]);
        }
        cs = (cs == 2 * GU_STG) ? 0 : cs + GU_STG;
    }

    // ---- epilogue: U via smem (stride 66), gate warps emit H ----------------
    float* Us = (float*)sm;
    if (mat == 1) {
        #pragma unroll
        for (int f = 0; f < 4; ++f) {
            const int r = R + 16 * f + row4;
            #pragma unroll
            for (int g = 0; g < 4; ++g) {
                const int c = nOff + g * 8 + kq * 2;
                *(float2*)(Us + r * 66 + c)       = make_float2(d[f][g][0], d[f][g][1]);
                *(float2*)(Us + (r + 8) * 66 + c) = make_float2(d[f][g][2], d[f][g][3]);
            }
        }
    }
    __syncthreads();
    if (mat == 0) {
        #pragma unroll
        for (int f = 0; f < 4; ++f) {
            const int r = R + 16 * f + row4;
            #pragma unroll
            for (int g = 0; g < 4; ++g) {
                const int c = nOff + g * 8 + kq * 2;
                const float2 u0 = *(const float2*)(Us + r * 66 + c);
                const float2 u1 = *(const float2*)(Us + (r + 8) * 66 + c);
                float2 v0, v1;
                v0.x = rnd_tf32(silu(d[f][g][0]) * u0.x);
                v0.y = rnd_tf32(silu(d[f][g][1]) * u0.y);
                v1.x = rnd_tf32(silu(d[f][g][2]) * u1.x);
                v1.y = rnd_tf32(silu(d[f][g][3]) * u1.y);
                *(float2*)(Out + (size_t)(mBase + r) * 1024 + nBase + c) = v0;
                *(float2*)(Out + (size_t)(mBase + r + 8) * 1024 + nBase + c) = v1;
            }
        }
    }
}

// =============================================================================
// Down GEMM. CTA 128x128, 8 warps (2m x 4n), warp tile 64x32. Plain store.
// smem/stage: A 128x36 (18432) + B 32x136 f32 (17408) = 35840. 3 stages.
// =============================================================================
#define DN_AS    36
#define DN_BS    136
#define DN_AB    18432
#define DN_STG   35840
#define DN_SMEM  (3 * DN_STG + 512)

__global__ void __launch_bounds__(256, 2) gemm_dn(
    const float* __restrict__ A,
    const float* __restrict__ Bg,
    float* __restrict__ Out)
{
    extern __shared__ char sm[];
    const uint32_t smem = smem_u32(sm);
    int* srcRow = (int*)(sm + 3 * DN_STG);

    const int tid  = threadIdx.x;
    const int wid  = tid >> 5;
    const int lane = tid & 31;
    const int row4 = lane >> 2;
    const int kq   = lane & 3;
    const int R    = (wid >> 2) * 64;
    const int nOff = (wid & 3) * 32;

    const int mBase = (blockIdx.z * gridDim.x + blockIdx.x) * 128;
    const int nBase = blockIdx.y * 128;

    if (tid < 128) srcRow[tid] = mBase + tid;
    __syncthreads();

    const float* B = Bg + (size_t)blockIdx.z * (1024u * 1024u);

    const float* aSrc[4]; uint32_t aDst[4];
    const float* bSrc[4]; uint32_t bDst[4];
    #pragma unroll
    for (int it = 0; it < 4; ++it) {
        const int ia = tid + it * 256;
        const int r = ia >> 3, q = ia & 7;
        aSrc[it] = A + (size_t)srcRow[r] * 1024 + q * 4;
        aDst[it] = smem + r * (DN_AS * 4) + q * 16;
        const int kk = ia >> 5, n4 = ia & 31;           // B: 32 k x 32 f4
        bSrc[it] = B + (size_t)kk * 1024 + nBase + n4 * 4;
        bDst[it] = smem + DN_AB + kk * (DN_BS * 4) + n4 * 16;
    }

    const int lr = lane & 7, hi8 = (lane >> 3) & 1, kHalf = lane >> 4;
    const uint32_t aLdBase =
        smem + ((R + hi8 * 8 + lr) * DN_AS + kHalf * 4) * 4;

    float d[4][4][4];
    #pragma unroll
    for (int f = 0; f < 4; ++f)
        #pragma unroll
        for (int g = 0; g < 4; ++g)
            #pragma unroll
            for (int j = 0; j < 4; ++j) d[f][g][j] = 0.f;

    auto issue = [&](int kt, uint32_t soff) {
        const int k0 = kt * 32;
        #pragma unroll
        for (int it = 0; it < 4; ++it)
            cp_async16(aDst[it] + soff, aSrc[it] + k0);
        #pragma unroll
        for (int it = 0; it < 4; ++it)
            cp_async16(bDst[it] + soff, bSrc[it] + (size_t)k0 * 1024);
        cp_commit();
    };

    issue(0, 0);
    issue(1, DN_STG);

    uint32_t cs = 0, ns = 2 * DN_STG;
    for (int kt = 0; kt < 32; ++kt) {
        if (kt < 31) cp_wait<1>(); else cp_wait<0>();
        __syncthreads();
        if (kt < 30) {
            issue(kt + 2, ns);
            ns = (ns == 2 * DN_STG) ? 0 : ns + DN_STG;
        }
        const uint32_t* Bs = (const uint32_t*)(sm + cs + DN_AB);
        const uint32_t aOff = aLdBase + cs;

        #pragma unroll
        for (int kk = 0; kk < 4; ++kk) {
            const int k = kk * 8;
            uint32_t af[4][4];
            #pragma unroll
            for (int f = 0; f < 4; ++f)
                ldsm_x4(af[f], aOff + f * (16 * DN_AS * 4) + kk * 32);
            uint32_t bf[4][2];
            #pragma unroll
            for (int g = 0; g < 4; ++g) {
                const int c = nOff + g * 8 + row4;
                bf[g][0] = Bs[(k + kq) * DN_BS + c];
                bf[g][1] = Bs[(k + kq + 4) * DN_BS + c];
            }
            #pragma unroll
            for (int f = 0; f < 4; ++f)
                #pragma unroll
                for (int g = 0; g < 4; ++g)
                    mma_tf32(d[f][g], af[f], bf[g]);
        }
        cs = (cs == 2 * DN_STG) ? 0 : cs + DN_STG;
    }

    #pragma unroll
    for (int f = 0; f < 4; ++f) {
        const int r = mBase + R + 16 * f + row4;
        #pragma unroll
        for (int g = 0; g < 4; ++g) {
            const int c = nBase + nOff + g * 8 + kq * 2;
            *(float2*)(Out + (size_t)r * 1024 + c) =
                make_float2(d[f][g][0], d[f][g][1]);
            *(float2*)(Out + (size_t)(r + 8) * 1024 + c) =
                make_float2(d[f][g][2], d[f][g][3]);
        }
    }
}

// =============================================================================
// Final combine: out[t] = w0*Y[inv[2t]] + w1*Y[inv[2t+1]] + sigmoid(x.gw)*S[t]
// =============================================================================
__global__ void __launch_bounds__(256) combine_kernel(
    const float* __restrict__ X, const float* __restrict__ tw,
    const float* __restrict__ gw, float* __restrict__ out)
{
    const int t = blockIdx.x;
    const int tid = threadIdx.x;
    __shared__ float red[256];
    const float* xr = X + (size_t)t * 1024;
    float acc = 0.f;
    #pragma unroll
    for (int it = 0; it < 4; ++it) {
        const int dd = tid + it * 256;
        acc += xr[dd] * gw[dd];
    }
    red[tid] = acc;
    __syncthreads();
    for (int s = 128; s > 0; s >>= 1) {
        if (tid < s) red[tid] += red[tid + s];
        __syncthreads();
    }
    const float g = 1.f / (1.f + __expf(-red[0]));
    const int r0 = g_inv[2 * t], r1 = g_inv[2 * t + 1];
    const float w0 = tw[2 * t], w1 = tw[2 * t + 1];
    const float4 a = ((const float4*)(g_Y + (size_t)r0 * 1024))[tid];
    const float4 b = ((const float4*)(g_Y + (size_t)r1 * 1024))[tid];
    const float4 c = ((const float4*)(g_S + (size_t)t  * 1024))[tid];
    float4 r;
    r.x = w0 * a.x + w1 * b.x + g * c.x;
    r.y = w0 * a.y + w1 * b.y + g * c.y;
    r.z = w0 * a.z + w1 * b.z + g * c.z;
    r.w = w0 * a.w + w1 * b.w + g * c.w;
    ((float4*)(out + (size_t)t * 1024))[tid] = r;
}

// =============================================================================
extern "C" void kernel_launch(void* const* d_in, const int* in_sizes, int n_in,
                              void* d_out, int out_size) {
    (void)in_sizes; (void)n_in; (void)out_size;
    const float* X   = (const float*)d_in[0];
    const float* tw  = (const float*)d_in[1];
    const float* wg  = (const float*)d_in[2];
    const float* wu  = (const float*)d_in[3];
    const float* wd  = (const float*)d_in[4];
    const float* swg = (const float*)d_in[5];
    const float* swu = (const float*)d_in[6];
    const float* swd = (const float*)d_in[7];
    const float* gw  = (const float*)d_in[8];
    const int*   tki = (const int*)d_in[9];
    float* out = (float*)d_out;

    float *H, *Y, *SH, *S, *Xr, *Wg, *Wu, *Wd, *Sg, *Su, *Sd;
    cudaGetSymbolAddress((void**)&H,  g_H);
    cudaGetSymbolAddress((void**)&Y,  g_Y);
    cudaGetSymbolAddress((void**)&SH, g_SH);
    cudaGetSymbolAddress((void**)&S,  g_S);
    cudaGetSymbolAddress((void**)&Xr, g_X);
    cudaGetSymbolAddress((void**)&Wg, g_wg);
    cudaGetSymbolAddress((void**)&Wu, g_wu);
    cudaGetSymbolAddress((void**)&Wd, g_wd);
    cudaGetSymbolAddress((void**)&Sg, g_swg);
    cudaGetSymbolAddress((void**)&Su, g_swu);
    cudaGetSymbolAddress((void**)&Sd, g_swd);

    cudaFuncSetAttribute(gemm_gu<true >, cudaFuncAttributeMaxDynamicSharedMemorySize, GU_SMEM);
    cudaFuncSetAttribute(gemm_gu<false>, cudaFuncAttributeMaxDynamicSharedMemorySize, GU_SMEM);
    cudaFuncSetAttribute(gemm_dn,        cudaFuncAttributeMaxDynamicSharedMemorySize, DN_SMEM);

    // 0. tf32 pre-round + dispatch permutation
    cvt_all<<<1184, 256>>>(X, wg, wu, wd, swg, swu, swd);
    build_perm_kernel<<<NEXP, 256>>>(tki);
    // 1. routed gate+up fused -> H = rnd(silu(Xp@Wg) * (Xp@Wu))
    gemm_gu<true ><<<dim3(8, 16, NEXP), 256, GU_SMEM>>>(Xr, Wg, Wu, H);
    // 2. routed down -> Y
    gemm_dn<<<dim3(8, 8, NEXP), 256, DN_SMEM>>>(H, Wd, Y);
    // 3. shared gate+up fused -> SH
    gemm_gu<false><<<dim3(32, 16, 1), 256, GU_SMEM>>>(Xr, Sg, Su, SH);
    // 4. shared down -> S
    gemm_dn<<<dim3(32, 8, 1), 256, DN_SMEM>>>(SH, Sd, S);
    // 5. combine
    combine_kernel<<<NTOK, 256>>>(X, tw, gw, out);
}

// round 5
// speedup vs baseline: 1.9972x; 1.4925x over previous
#include <cuda_runtime.h>
#include <cuda_fp16.h>
#include <cstdint>

// =============================================================================
// MoE fused layer, plain sm_103 target. R5: full fp16 datapath with
// mma.sync.m16n8k16 (fp32 accum), ldmatrix for A and (trans) B -> no scalar
// LDS in the mainloop. 128-thr CTAs, warp tile 64x64, CTA 128x128, K-chunk 64,
// 3-stage cp.async, 2 CTAs/SM.
// T=4096, D=1024, E=8, K=2, F=SF=1024.
// =============================================================================

#define NEXP   8
#define NTOK   4096
#define NROWS  8192
#define CPE    1024

// ---------------- scratch (device globals) -----------------------------------
__device__ __align__(16) __half g_hX  [4096u * 1024u];
__device__ __align__(16) __half g_hwg [8u * 1024u * 1024u];
__device__ __align__(16) __half g_hwu [8u * 1024u * 1024u];
__device__ __align__(16) __half g_hwd [8u * 1024u * 1024u];
__device__ __align__(16) __half g_hswg[1024u * 1024u];
__device__ __align__(16) __half g_hswu[1024u * 1024u];
__device__ __align__(16) __half g_hswd[1024u * 1024u];
__device__ __align__(16) __half g_H [8192u * 1024u];  // routed hidden (fp16)
__device__ __align__(16) __half g_SH[4096u * 1024u];  // shared hidden (fp16)
__device__ float g_Y [8192u * 1024u];                  // routed down out (fp32)
__device__ float g_S [4096u * 1024u];                  // shared down out (fp32)
__device__ int   g_perm[8192];
__device__ int   g_inv [8192];

// ---------------- helpers ------------------------------------------------------
__device__ __forceinline__ uint32_t smem_u32(const void* p) {
    uint32_t a;
    asm("{ .reg .u64 t; cvta.to.shared.u64 t, %1; cvt.u32.u64 %0, t; }"
        : "=r"(a) : "l"(p));
    return a;
}
__device__ __forceinline__ void cp_async16(uint32_t dst, const void* src) {
    asm volatile("cp.async.cg.shared.global [%0], [%1], 16;"
                 :: "r"(dst), "l"(src) : "memory");
}
__device__ __forceinline__ void cp_commit() {
    asm volatile("cp.async.commit_group;" ::: "memory");
}
template<int N>
__device__ __forceinline__ void cp_wait() {
    asm volatile("cp.async.wait_group %0;" :: "n"(N) : "memory");
}
__device__ __forceinline__ void ldsm_x4(uint32_t* r, uint32_t addr) {
    asm volatile("ldmatrix.sync.aligned.m8n8.x4.shared.b16 {%0,%1,%2,%3}, [%4];"
                 : "=r"(r[0]), "=r"(r[1]), "=r"(r[2]), "=r"(r[3]) : "r"(addr));
}
__device__ __forceinline__ void ldsm_x4t(uint32_t* r, uint32_t addr) {
    asm volatile("ldmatrix.sync.aligned.m8n8.x4.trans.shared.b16 {%0,%1,%2,%3}, [%4];"
                 : "=r"(r[0]), "=r"(r[1]), "=r"(r[2]), "=r"(r[3]) : "r"(addr));
}
__device__ __forceinline__ void mma_f16(float* d, const uint32_t* a,
                                        const uint32_t* b) {
    asm volatile(
        "mma.sync.aligned.m16n8k16.row.col.f32.f16.f16.f32 "
        "{%0,%1,%2,%3}, {%4,%5,%6,%7}, {%8,%9}, {%0,%1,%2,%3};"
        : "+f"(d[0]), "+f"(d[1]), "+f"(d[2]), "+f"(d[3])
        : "r"(a[0]), "r"(a[1]), "r"(a[2]), "r"(a[3]), "r"(b[0]), "r"(b[1]));
}
__device__ __forceinline__ float silu(float x) {
    return x / (1.f + __expf(-x));
}

// =============================================================================
// fp32 -> fp16 conversion of all MMA inputs.
// =============================================================================
__global__ void __launch_bounds__(256) cvt_all(
    const float* __restrict__ x,
    const float* __restrict__ wg,  const float* __restrict__ wu,
    const float* __restrict__ wd,
    const float* __restrict__ swg, const float* __restrict__ swu,
    const float* __restrict__ swd)
{
    const size_t total = 8126464u;   // float4 units
    for (size_t i = (size_t)blockIdx.x * blockDim.x + threadIdx.x;
         i < total; i += (size_t)gridDim.x * blockDim.x) {
        const float4* s; __half2* d; size_t j;
        if      (i < 1048576u) { s = (const float4*)x;   d = (__half2*)g_hX;   j = i; }
        else if (i < 3145728u) { s = (const float4*)wg;  d = (__half2*)g_hwg;  j = i - 1048576u; }
        else if (i < 5242880u) { s = (const float4*)wu;  d = (__half2*)g_hwu;  j = i - 3145728u; }
        else if (i < 7340032u) { s = (const float4*)wd;  d = (__half2*)g_hwd;  j = i - 5242880u; }
        else if (i < 7602176u) { s = (const float4*)swg; d = (__half2*)g_hswg; j = i - 7340032u; }
        else if (i < 7864320u) { s = (const float4*)swu; d = (__half2*)g_hswu; j = i - 7602176u; }
        else                   { s = (const float4*)swd; d = (__half2*)g_hswd; j = i - 7864320u; }
        const float4 v = s[j];
        d[2 * j]     = __floats2half2_rn(v.x, v.y);
        d[2 * j + 1] = __floats2half2_rn(v.z, v.w);
    }
}

// =============================================================================
// Stable counting-sort permutation (matches jnp.argsort stability).
// =============================================================================
__global__ void build_perm_kernel(const int* __restrict__ tki) {
    const int e = blockIdx.x;
    const int tid = threadIdx.x;
    __shared__ int scan[256];
    __shared__ int basev;
    if (tid == 0) basev = 0;
    __syncthreads();
    for (int start = 0; start < NROWS; start += 256) {
        const int i = start + tid;
        const int m = (tki[i] == e) ? 1 : 0;
        scan[tid] = m;
        __syncthreads();
        #pragma unroll
        for (int off = 1; off < 256; off <<= 1) {
            int v = (tid >= off) ? scan[tid - off] : 0;
            __syncthreads();
            scan[tid] += v;
            __syncthreads();
        }
        if (m) {
            const int dest = e * CPE + basev + scan[tid] - 1;
            g_perm[dest] = i;
            g_inv[i] = dest;
        }
        __syncthreads();
        if (tid == 0) basev += scan[255];
        __syncthreads();
    }
}

// =============================================================================
// Shared GEMM machinery (fp16). A smem rows: 64 data halfs + 8 pad = stride 72
// halfs (144 B). B smem rows (k-major): stride BSTR halfs.
// =============================================================================
#define A_STRH 72
#define A_BYTES 18432            // 128 * 144

// ---------- fused gate+up: CTA 128m x 64n, warps 0-1 gate, 2-3 up -------------
#define GU_BSTRH 72              // 64 data + 8 pad
#define GU_BMAT  9216            // 64 * 144
#define GU_STG   36864           // A 18432 + 2*9216
#define GU_SMEM  (3 * GU_STG + 512)

template<bool GATHER>
__global__ void __launch_bounds__(128, 2) gemm_gu(
    const __half* __restrict__ A,
    const __half* __restrict__ B0g,
    const __half* __restrict__ B1g,
    __half* __restrict__ Out)
{
    extern __shared__ char sm[];
    const uint32_t smem = smem_u32(sm);
    int* srcRow = (int*)(sm + 3 * GU_STG);

    const int tid  = threadIdx.x;
    const int wid  = tid >> 5;
    const int lane = tid & 31;
    const int row4 = lane >> 2;
    const int kq   = lane & 3;
    const int mat  = wid >> 1;          // 0 gate, 1 up
    const int wm   = wid & 1;           // m half

    const int mBase = (blockIdx.z * gridDim.x + blockIdx.x) * 128;
    const int nBase = blockIdx.y * 64;

    srcRow[tid] = GATHER ? (g_perm[mBase + tid] >> 1) : (mBase + tid);
    __syncthreads();

    const __half* B0 = B0g + (size_t)blockIdx.z * (1024u * 1024u);
    const __half* B1 = B1g + (size_t)blockIdx.z * (1024u * 1024u);

    // cp.async endpoints: A 1024 units, B 1024 units; 128 thr -> 8+8 per thread
    const __half* aSrc[8]; uint32_t aDst[8];
    const __half* bSrc[8]; uint32_t bDst[8];
    #pragma unroll
    for (int it = 0; it < 8; ++it) {
        const int ia = tid + it * 128;
        const int r = ia >> 3, q = ia & 7;               // A: 128 rows x 8 units
        aSrc[it] = A + (size_t)srcRow[r] * 1024 + q * 8;
        aDst[it] = smem + r * 144 + q * 16;
        const int mm = ia >> 9, kr = (ia >> 3) & 63, qb = ia & 7;
        bSrc[it] = (mm ? B1 : B0) + (size_t)kr * 1024 + nBase + qb * 8;
        bDst[it] = smem + A_BYTES + mm * GU_BMAT + kr * 144 + qb * 16;
    }

    // ldmatrix lane bases
    const int rl = lane & 7, sel = lane >> 3;
    const uint32_t aBase = smem +
        (wm * 64 + (sel & 1) * 8 + rl) * 144 + (sel >> 1) * 16;
    const uint32_t bBase = smem + A_BYTES + mat * GU_BMAT +
        ((sel & 1) * 8 + rl) * 144 + ((sel >> 1) * 8) * 2;

    float d[4][8][4];
    #pragma unroll
    for (int f = 0; f < 4; ++f)
        #pragma unroll
        for (int g = 0; g < 8; ++g)
            #pragma unroll
            for (int j = 0; j < 4; ++j) d[f][g][j] = 0.f;

    auto issue = [&](int ch, uint32_t soff) {
        const int k0 = ch * 64;
        #pragma unroll
        for (int it = 0; it < 8; ++it)
            cp_async16(aDst[it] + soff, aSrc[it] + k0);
        #pragma unroll
        for (int it = 0; it < 8; ++it)
            cp_async16(bDst[it] + soff, bSrc[it] + (size_t)k0 * 1024);
        cp_commit();
    };

    issue(0, 0);
    issue(1, GU_STG);

    uint32_t cs = 0, ns = 2 * GU_STG;
    for (int ch = 0; ch < 16; ++ch) {
        if (ch < 15) cp_wait<1>(); else cp_wait<0>();
        __syncthreads();
        if (ch < 14) {
            issue(ch + 2, ns);
            ns = (ns == 2 * GU_STG) ? 0 : ns + GU_STG;
        }
        #pragma unroll
        for (int ks = 0; ks < 4; ++ks) {
            uint32_t af[4][4];
            #pragma unroll
            for (int f = 0; f < 4; ++f)
                ldsm_x4(af[f], aBase + cs + f * 2304 + ks * 32);
            uint32_t bf[4][4];          // bf[g2]: n-frags 2g2, 2g2+1
            #pragma unroll
            for (int g2 = 0; g2 < 4; ++g2)
                ldsm_x4t(bf[g2], bBase + cs + ks * (16 * 144) + g2 * 32);
            #pragma unroll
            for (int f = 0; f < 4; ++f)
                #pragma unroll
                for (int g = 0; g < 8; ++g)
                    mma_f16(d[f][g], af[f], &bf[g >> 1][(g & 1) * 2]);
        }
        cs = (cs == 2 * GU_STG) ? 0 : cs + GU_STG;
    }

    // ---- epilogue: up warps stage U (fp32) in smem; gate warps emit H -------
    __syncthreads();
    float* Us = (float*)sm;             // [128][66]
    if (mat == 1) {
        #pragma unroll
        for (int f = 0; f < 4; ++f) {
            const int r = wm * 64 + f * 16 + row4;
            #pragma unroll
            for (int g = 0; g < 8; ++g) {
                const int c = g * 8 + kq * 2;
                *(float2*)(Us + r * 66 + c)       = make_float2(d[f][g][0], d[f][g][1]);
                *(float2*)(Us + (r + 8) * 66 + c) = make_float2(d[f][g][2], d[f][g][3]);
            }
        }
    }
    __syncthreads();
    if (mat == 0) {
        #pragma unroll
        for (int f = 0; f < 4; ++f) {
            const int r = wm * 64 + f * 16 + row4;
            #pragma unroll
            for (int g = 0; g < 8; ++g) {
                const int c = g * 8 + kq * 2;
                const float2 u0 = *(const float2*)(Us + r * 66 + c);
                const float2 u1 = *(const float2*)(Us + (r + 8) * 66 + c);
                const __half2 h0 = __floats2half2_rn(silu(d[f][g][0]) * u0.x,
                                                     silu(d[f][g][1]) * u0.y);
                const __half2 h1 = __floats2half2_rn(silu(d[f][g][2]) * u1.x,
                                                     silu(d[f][g][3]) * u1.y);
                *(__half2*)(Out + (size_t)(mBase + r) * 1024 + nBase + c) = h0;
                *(__half2*)(Out + (size_t)(mBase + r + 8) * 1024 + nBase + c) = h1;
            }
        }
    }
}

// ---------- down GEMM: CTA 128m x 128n, 4 warps (2m x 2n), warp 64x64 ---------
#define DN_BSTRH 136             // 128 data + 8 pad
#define DN_BB    17408           // 64 * 272
#define DN_STG   35840           // A 18432 + B 17408
#define DN_SMEM  (3 * DN_STG + 256)

__global__ void __launch_bounds__(128, 2) gemm_dn(
    const __half* __restrict__ A,
    const __half* __restrict__ Bg,
    float* __restrict__ Out)
{
    extern __shared__ char sm[];
    const uint32_t smem = smem_u32(sm);

    const int tid  = threadIdx.x;
    const int wid  = tid >> 5;
    const int lane = tid & 31;
    const int row4 = lane >> 2;
    const int kq   = lane & 3;
    const int wm   = wid & 1;
    const int nOff = (wid >> 1) * 64;

    const int mBase = (blockIdx.z * gridDim.x + blockIdx.x) * 128;
    const int nBase = blockIdx.y * 128;

    const __half* B = Bg + (size_t)blockIdx.z * (1024u * 1024u);

    const __half* aSrc[8]; uint32_t aDst[8];
    const __half* bSrc[8]; uint32_t bDst[8];
    #pragma unroll
    for (int it = 0; it < 8; ++it) {
        const int ia = tid + it * 128;
        const int r = ia >> 3, q = ia & 7;
        aSrc[it] = A + (size_t)(mBase + r) * 1024 + q * 8;
        aDst[it] = smem + r * 144 + q * 16;
        const int kr = ia >> 4, qb = ia & 15;            // B: 64 rows x 16 units
        bSrc[it] = B + (size_t)kr * 1024 + nBase + qb * 8;
        bDst[it] = smem + A_BYTES + kr * 272 + qb * 16;
    }

    const int rl = lane & 7, sel = lane >> 3;
    const uint32_t aBase = smem +
        (wm * 64 + (sel & 1) * 8 + rl) * 144 + (sel >> 1) * 16;
    const uint32_t bBase = smem + A_BYTES +
        ((sel & 1) * 8 + rl) * 272 + (nOff + (sel >> 1) * 8) * 2;

    float d[4][8][4];
    #pragma unroll
    for (int f = 0; f < 4; ++f)
        #pragma unroll
        for (int g = 0; g < 8; ++g)
            #pragma unroll
            for (int j = 0; j < 4; ++j) d[f][g][j] = 0.f;

    auto issue = [&](int ch, uint32_t soff) {
        const int k0 = ch * 64;
        #pragma unroll
        for (int it = 0; it < 8; ++it)
            cp_async16(aDst[it] + soff, aSrc[it] + k0);
        #pragma unroll
        for (int it = 0; it < 8; ++it)
            cp_async16(bDst[it] + soff, bSrc[it] + (size_t)k0 * 1024);
        cp_commit();
    };

    issue(0, 0);
    issue(1, DN_STG);

    uint32_t cs = 0, ns = 2 * DN_STG;
    for (int ch = 0; ch < 16; ++ch) {
        if (ch < 15) cp_wait<1>(); else cp_wait<0>();
        __syncthreads();
        if (ch < 14) {
            issue(ch + 2, ns);
            ns = (ns == 2 * DN_STG) ? 0 : ns + DN_STG;
        }
        #pragma unroll
        for (int ks = 0; ks < 4; ++ks) {
            uint32_t af[4][4];
            #pragma unroll
            for (int f = 0; f < 4; ++f)
                ldsm_x4(af[f], aBase + cs + f * 2304 + ks * 32);
            uint32_t bf[4][4];
            #pragma unroll
            for (int g2 = 0; g2 < 4; ++g2)
                ldsm_x4t(bf[g2], bBase + cs + ks * (16 * 272) + g2 * 32);
            #pragma unroll
            for (int f = 0; f < 4; ++f)
                #pragma unroll
                for (int g = 0; g < 8; ++g)
                    mma_f16(d[f][g], af[f], &bf[g >> 1][(g & 1) * 2]);
        }
        cs = (cs == 2 * DN_STG) ? 0 : cs + DN_STG;
    }

    #pragma unroll
    for (int f = 0; f < 4; ++f) {
        const int r = mBase + wm * 64 + f * 16 + row4;
        #pragma unroll
        for (int g = 0; g < 8; ++g) {
            const int c = nBase + nOff + g * 8 + kq * 2;
            *(float2*)(Out + (size_t)r * 1024 + c) =
                make_float2(d[f][g][0], d[f][g][1]);
            *(float2*)(Out + (size_t)(r + 8) * 1024 + c) =
                make_float2(d[f][g][2], d[f][g][3]);
        }
    }
}

// =============================================================================
// Final combine: out[t] = w0*Y[inv[2t]] + w1*Y[inv[2t+1]] + sigmoid(x.gw)*S[t]
// =============================================================================
__global__ void __launch_bounds__(256) combine_kernel(
    const float* __restrict__ X, const float* __restrict__ tw,
    const float* __restrict__ gw, float* __restrict__ out)
{
    const int t = blockIdx.x;
    const int tid = threadIdx.x;
    __shared__ float red[256];
    const float* xr = X + (size_t)t * 1024;
    float acc = 0.f;
    #pragma unroll
    for (int it = 0; it < 4; ++it) {
        const int dd = tid + it * 256;
        acc += xr[dd] * gw[dd];
    }
    red[tid] = acc;
    __syncthreads();
    for (int s = 128; s > 0; s >>= 1) {
        if (tid < s) red[tid] += red[tid + s];
        __syncthreads();
    }
    const float g = 1.f / (1.f + __expf(-red[0]));
    const int r0 = g_inv[2 * t], r1 = g_inv[2 * t + 1];
    const float w0 = tw[2 * t], w1 = tw[2 * t + 1];
    const float4 a = ((const float4*)(g_Y + (size_t)r0 * 1024))[tid];
    const float4 b = ((const float4*)(g_Y + (size_t)r1 * 1024))[tid];
    const float4 c = ((const float4*)(g_S + (size_t)t  * 1024))[tid];
    float4 r;
    r.x = w0 * a.x + w1 * b.x + g * c.x;
    r.y = w0 * a.y + w1 * b.y + g * c.y;
    r.z = w0 * a.z + w1 * b.z + g * c.z;
    r.w = w0 * a.w + w1 * b.w + g * c.w;
    ((float4*)(out + (size_t)t * 1024))[tid] = r;
}

// =============================================================================
extern "C" void kernel_launch(void* const* d_in, const int* in_sizes, int n_in,
                              void* d_out, int out_size) {
    (void)in_sizes; (void)n_in; (void)out_size;
    const float* X   = (const float*)d_in[0];
    const float* tw  = (const float*)d_in[1];
    const float* wg  = (const float*)d_in[2];
    const float* wu  = (const float*)d_in[3];
    const float* wd  = (const float*)d_in[4];
    const float* swg = (const float*)d_in[5];
    const float* swu = (const float*)d_in[6];
    const float* swd = (const float*)d_in[7];
    const float* gw  = (const float*)d_in[8];
    const int*   tki = (const int*)d_in[9];
    float* out = (float*)d_out;

    __half *hX, *hWg, *hWu, *hWd, *hSg, *hSu, *hSd, *H, *SH;
    float *Y, *S;
    cudaGetSymbolAddress((void**)&hX,  g_hX);
    cudaGetSymbolAddress((void**)&hWg, g_hwg);
    cudaGetSymbolAddress((void**)&hWu, g_hwu);
    cudaGetSymbolAddress((void**)&hWd, g_hwd);
    cudaGetSymbolAddress((void**)&hSg, g_hswg);
    cudaGetSymbolAddress((void**)&hSu, g_hswu);
    cudaGetSymbolAddress((void**)&hSd, g_hswd);
    cudaGetSymbolAddress((void**)&H,   g_H);
    cudaGetSymbolAddress((void**)&SH,  g_SH);
    cudaGetSymbolAddress((void**)&Y,   g_Y);
    cudaGetSymbolAddress((void**)&S,   g_S);

    cudaFuncSetAttribute(gemm_gu<true >, cudaFuncAttributeMaxDynamicSharedMemorySize, GU_SMEM);
    cudaFuncSetAttribute(gemm_gu<false>, cudaFuncAttributeMaxDynamicSharedMemorySize, GU_SMEM);
    cudaFuncSetAttribute(gemm_dn,        cudaFuncAttributeMaxDynamicSharedMemorySize, DN_SMEM);

    // 0. fp16 conversion + dispatch permutation
    cvt_all<<<1184, 256>>>(X, wg, wu, wd, swg, swu, swd);
    build_perm_kernel<<<NEXP, 256>>>(tki);
    // 1. routed gate+up fused -> H = fp16(silu(Xp@Wg) * (Xp@Wu))
    gemm_gu<true ><<<dim3(8, 16, NEXP), 128, GU_SMEM>>>(hX, hWg, hWu, H);
    // 2. routed down -> Y (fp32)
    gemm_dn<<<dim3(8, 8, NEXP), 128, DN_SMEM>>>(H, hWd, Y);
    // 3. shared gate+up fused -> SH
    gemm_gu<false><<<dim3(32, 16, 1), 128, GU_SMEM>>>(hX, hSg, hSu, SH);
    // 4. shared down -> S (fp32)
    gemm_dn<<<dim3(32, 8, 1), 128, DN_SMEM>>>(SH, hSd, S);
    // 5. combine
    combine_kernel<<<NTOK, 256>>>(X, tw, gw, out);
}

// round 7
// speedup vs baseline: 2.2535x; 1.1283x over previous
#include <cuda_runtime.h>
#include <cuda_fp16.h>
#include <cstdint>

// =============================================================================
// MoE fused layer, plain sm_103. R7: GU converted to 256-thr / warp tile 64x32
// (16 warps/SM); DN kept at known-good R5 geometry (128-thr / 64x64).
// fp16 mma.sync m16n8k16, fp32 accum. T=4096, D=1024, E=8, K=2, F=SF=1024.
// =============================================================================

#define NEXP   8
#define NTOK   4096
#define NROWS  8192
#define CPE    1024

// ---------------- device-global scratch --------------------------------------
__device__ __align__(16) __half g_hX  [4096u * 1024u];
__device__ __align__(16) __half g_hwg [8u * 1024u * 1024u];
__device__ __align__(16) __half g_hwu [8u * 1024u * 1024u];
__device__ __align__(16) __half g_hwd [8u * 1024u * 1024u];
__device__ __align__(16) __half g_hswg[1024u * 1024u];
__device__ __align__(16) __half g_hswu[1024u * 1024u];
__device__ __align__(16) __half g_hswd[1024u * 1024u];
__device__ __align__(16) __half g_H [8192u * 1024u];
__device__ __align__(16) __half g_SH[4096u * 1024u];
__device__ float g_Y [8192u * 1024u];
__device__ float g_S [4096u * 1024u];
__device__ int   g_perm[8192];
__device__ int   g_inv [8192];

// ---------------- helpers ------------------------------------------------------
__device__ __forceinline__ uint32_t smem_u32(const void* p) {
    uint32_t a;
    asm("{ .reg .u64 t; cvta.to.shared.u64 t, %1; cvt.u32.u64 %0, t; }"
        : "=r"(a) : "l"(p));
    return a;
}
__device__ __forceinline__ void cp_async16(uint32_t dst, const void* src) {
    asm volatile("cp.async.cg.shared.global [%0], [%1], 16;"
                 :: "r"(dst), "l"(src) : "memory");
}
__device__ __forceinline__ void cp_commit() {
    asm volatile("cp.async.commit_group;" ::: "memory");
}
template<int N>
__device__ __forceinline__ void cp_wait() {
    asm volatile("cp.async.wait_group %0;" :: "n"(N) : "memory");
}
__device__ __forceinline__ void ldsm_x4(uint32_t* r, uint32_t addr) {
    asm volatile("ldmatrix.sync.aligned.m8n8.x4.shared.b16 {%0,%1,%2,%3}, [%4];"
                 : "=r"(r[0]), "=r"(r[1]), "=r"(r[2]), "=r"(r[3]) : "r"(addr));
}
__device__ __forceinline__ void ldsm_x4t(uint32_t* r, uint32_t addr) {
    asm volatile("ldmatrix.sync.aligned.m8n8.x4.trans.shared.b16 {%0,%1,%2,%3}, [%4];"
                 : "=r"(r[0]), "=r"(r[1]), "=r"(r[2]), "=r"(r[3]) : "r"(addr));
}
__device__ __forceinline__ void mma_f16(float* d, const uint32_t* a,
                                        const uint32_t* b) {
    asm volatile(
        "mma.sync.aligned.m16n8k16.row.col.f32.f16.f16.f32 "
        "{%0,%1,%2,%3}, {%4,%5,%6,%7}, {%8,%9}, {%0,%1,%2,%3};"
        : "+f"(d[0]), "+f"(d[1]), "+f"(d[2]), "+f"(d[3])
        : "r"(a[0]), "r"(a[1]), "r"(a[2]), "r"(a[3]), "r"(b[0]), "r"(b[1]));
}
__device__ __forceinline__ float silu(float x) {
    return x / (1.f + __expf(-x));
}

// =============================================================================
// fp32 -> fp16 conversion of all MMA inputs.
// =============================================================================
__global__ void __launch_bounds__(256) cvt_all(
    const float* __restrict__ x,
    const float* __restrict__ wg,  const float* __restrict__ wu,
    const float* __restrict__ wd,
    const float* __restrict__ swg, const float* __restrict__ swu,
    const float* __restrict__ swd)
{
    const size_t total = 8126464u;   // float4 units
    for (size_t i = (size_t)blockIdx.x * blockDim.x + threadIdx.x;
         i < total; i += (size_t)gridDim.x * blockDim.x) {
        const float4* s; __half2* d; size_t j;
        if      (i < 1048576u) { s = (const float4*)x;   d = (__half2*)g_hX;   j = i; }
        else if (i < 3145728u) { s = (const float4*)wg;  d = (__half2*)g_hwg;  j = i - 1048576u; }
        else if (i < 5242880u) { s = (const float4*)wu;  d = (__half2*)g_hwu;  j = i - 3145728u; }
        else if (i < 7340032u) { s = (const float4*)wd;  d = (__half2*)g_hwd;  j = i - 5242880u; }
        else if (i < 7602176u) { s = (const float4*)swg; d = (__half2*)g_hswg; j = i - 7340032u; }
        else if (i < 7864320u) { s = (const float4*)swu; d = (__half2*)g_hswu; j = i - 7602176u; }
        else                   { s = (const float4*)swd; d = (__half2*)g_hswd; j = i - 7864320u; }
        const float4 v = s[j];
        d[2 * j]     = __floats2half2_rn(v.x, v.y);
        d[2 * j + 1] = __floats2half2_rn(v.z, v.w);
    }
}

// =============================================================================
// Stable counting-sort permutation (matches jnp.argsort stability).
// =============================================================================
__global__ void build_perm_kernel(const int* __restrict__ tki) {
    const int e = blockIdx.x;
    const int tid = threadIdx.x;
    __shared__ int scan[256];
    __shared__ int basev;
    if (tid == 0) basev = 0;
    __syncthreads();
    for (int start = 0; start < NROWS; start += 256) {
        const int i = start + tid;
        const int m = (tki[i] == e) ? 1 : 0;
        scan[tid] = m;
        __syncthreads();
        #pragma unroll
        for (int off = 1; off < 256; off <<= 1) {
            int v = (tid >= off) ? scan[tid - off] : 0;
            __syncthreads();
            scan[tid] += v;
            __syncthreads();
        }
        if (m) {
            const int dest = e * CPE + basev + scan[tid] - 1;
            g_perm[dest] = i;
            g_inv[i] = dest;
        }
        __syncthreads();
        if (tid == 0) basev += scan[255];
        __syncthreads();
    }
}

// =============================================================================
// Fused gate+up GEMM. 256 threads, 8 warps: warps 0-3 gate, 4-7 up; within a
// matrix group, (wm, wn2) = (wq>>1, wq&1); warp tile 64m x 32n.
// CTA: 128m x 64n for both matrices. K-chunk 64, 3 stages.
// smem/stage: A 128*144 (18432) + 2 * 64*144 (9216 each) = 36864.
// =============================================================================
#define GU_STG   36864
#define GU_SMEM  (3 * GU_STG + 512)

template<bool GATHER>
__global__ void __launch_bounds__(256, 2) gemm_gu(
    const __half* __restrict__ A,
    const __half* __restrict__ B0g,
    const __half* __restrict__ B1g,
    __half* __restrict__ Out)
{
    extern __shared__ char sm[];
    const uint32_t smem = smem_u32(sm);
    int* srcRow = (int*)(sm + 3 * GU_STG);

    const int tid  = threadIdx.x;
    const int wid  = tid >> 5;
    const int lane = tid & 31;
    const int row4 = lane >> 2;
    const int kq   = lane & 3;
    const int rl   = lane & 7;
    const int sel  = lane >> 3;
    const int mat  = wid >> 2;          // 0 gate, 1 up
    const int wm   = (wid >> 1) & 1;    // m half (64 rows)
    const int wn2  = wid & 1;           // n half (32 cols)

    const int mBase = (blockIdx.z * gridDim.x + blockIdx.x) * 128;
    const int nBase = blockIdx.y * 64;

    if (tid < 128)
        srcRow[tid] = GATHER ? (g_perm[mBase + tid] >> 1) : (mBase + tid);
    __syncthreads();

    const __half* B0 = B0g + (size_t)blockIdx.z * 1048576u;
    const __half* B1 = B1g + (size_t)blockIdx.z * 1048576u;

    // cp.async endpoints: exactly R5's ia-decomposition, 256 threads -> it<4.
    const __half* aSrc[4]; uint32_t aDst[4];
    const __half* bSrc[4]; uint32_t bDst[4];
    #pragma unroll
    for (int it = 0; it < 4; ++it) {
        const int ia = tid + it * 256;                   // 0..1023
        const int r = ia >> 3, q = ia & 7;               // A: 128 rows x 8 units
        aSrc[it] = A + (size_t)srcRow[r] * 1024 + q * 8;
        aDst[it] = smem + r * 144 + q * 16;
        const int mm = ia >> 9, kr = (ia >> 3) & 63, qb = ia & 7;
        bSrc[it] = (mm ? B1 : B0) + (size_t)kr * 1024 + nBase + qb * 8;
        bDst[it] = smem + 18432 + mm * 9216 + kr * 144 + qb * 16;
    }

    // ldmatrix lane bases
    const uint32_t aBase = smem + (wm * 64 + (sel & 1) * 8 + rl) * 144
                         + (sel >> 1) * 16;
    const uint32_t bBase = smem + 18432 + mat * 9216
                         + ((sel & 1) * 8 + rl) * 144
                         + (wn2 * 32 + (sel >> 1) * 8) * 2;

    float d[4][4][4];
    #pragma unroll
    for (int f = 0; f < 4; ++f)
        #pragma unroll
        for (int g = 0; g < 4; ++g)
            #pragma unroll
            for (int j = 0; j < 4; ++j) d[f][g][j] = 0.f;

    auto issue = [&](int ch, uint32_t soff) {
        const int k0 = ch * 64;
        #pragma unroll
        for (int it = 0; it < 4; ++it)
            cp_async16(aDst[it] + soff, aSrc[it] + k0);
        #pragma unroll
        for (int it = 0; it < 4; ++it)
            cp_async16(bDst[it] + soff, bSrc[it] + (size_t)k0 * 1024);
        cp_commit();
    };

    issue(0, 0);
    issue(1, GU_STG);

    uint32_t cs = 0, ns = 2 * GU_STG;
    for (int ch = 0; ch < 16; ++ch) {
        if (ch < 15) cp_wait<1>(); else cp_wait<0>();
        __syncthreads();
        if (ch < 14) {
            issue(ch + 2, ns);
            ns = (ns == 2 * GU_STG) ? 0 : ns + GU_STG;
        }
        #pragma unroll
        for (int ks = 0; ks < 4; ++ks) {
            uint32_t af[4][4];
            #pragma unroll
            for (int f = 0; f < 4; ++f)
                ldsm_x4(af[f], aBase + cs + f * 2304 + ks * 32);
            uint32_t bf[2][4];
            #pragma unroll
            for (int g2 = 0; g2 < 2; ++g2)
                ldsm_x4t(bf[g2], bBase + cs + ks * 2304 + g2 * 32);
            #pragma unroll
            for (int f = 0; f < 4; ++f)
                #pragma unroll
                for (int g = 0; g < 4; ++g)
                    mma_f16(d[f][g], af[f], &bf[g >> 1][(g & 1) * 2]);
        }
        cs = (cs == 2 * GU_STG) ? 0 : cs + GU_STG;
    }

    // ---- epilogue: up warps stage U in smem; gate warps emit fp16 H ---------
    __syncthreads();
    float* Us = (float*)sm;             // [128][66]
    if (mat == 1) {
        #pragma unroll
        for (int f = 0; f < 4; ++f) {
            const int r = wm * 64 + f * 16 + row4;
            #pragma unroll
            for (int g = 0; g < 4; ++g) {
                const int c = wn2 * 32 + g * 8 + kq * 2;
                *(float2*)(Us + r * 66 + c)       = make_float2(d[f][g][0], d[f][g][1]);
                *(float2*)(Us + (r + 8) * 66 + c) = make_float2(d[f][g][2], d[f][g][3]);
            }
        }
    }
    __syncthreads();
    if (mat == 0) {
        #pragma unroll
        for (int f = 0; f < 4; ++f) {
            const int r = wm * 64 + f * 16 + row4;
            #pragma unroll
            for (int g = 0; g < 4; ++g) {
                const int c = wn2 * 32 + g * 8 + kq * 2;
                const float2 u0 = *(const float2*)(Us + r * 66 + c);
                const float2 u1 = *(const float2*)(Us + (r + 8) * 66 + c);
                *(__half2*)(Out + (size_t)(mBase + r) * 1024 + nBase + c) =
                    __floats2half2_rn(silu(d[f][g][0]) * u0.x,
                                      silu(d[f][g][1]) * u0.y);
                *(__half2*)(Out + (size_t)(mBase + r + 8) * 1024 + nBase + c) =
                    __floats2half2_rn(silu(d[f][g][2]) * u1.x,
                                      silu(d[f][g][3]) * u1.y);
            }
        }
    }
}

// =============================================================================
// Down GEMM — R5 geometry verbatim (known good). CTA 128x128, 128 thr, 4 warps
// (2m x 2n), warp tile 64x64. smem/stage: A 18432 + B 64*272 (17408) = 35840.
// =============================================================================
#define DN_STG   35840
#define DN_SMEM  (3 * DN_STG + 256)

__global__ void __launch_bounds__(128, 2) gemm_dn(
    const __half* __restrict__ A,
    const __half* __restrict__ Bg,
    float* __restrict__ Out)
{
    extern __shared__ char sm[];
    const uint32_t smem = smem_u32(sm);

    const int tid  = threadIdx.x;
    const int wid  = tid >> 5;
    const int lane = tid & 31;
    const int row4 = lane >> 2;
    const int kq   = lane & 3;
    const int wm   = wid & 1;
    const int nOff = (wid >> 1) * 64;

    const int mBase = (blockIdx.z * gridDim.x + blockIdx.x) * 128;
    const int nBase = blockIdx.y * 128;

    const __half* B = Bg + (size_t)blockIdx.z * (1024u * 1024u);

    const __half* aSrc[8]; uint32_t aDst[8];
    const __half* bSrc[8]; uint32_t bDst[8];
    #pragma unroll
    for (int it = 0; it < 8; ++it) {
        const int ia = tid + it * 128;
        const int r = ia >> 3, q = ia & 7;
        aSrc[it] = A + (size_t)(mBase + r) * 1024 + q * 8;
        aDst[it] = smem + r * 144 + q * 16;
        const int kr = ia >> 4, qb = ia & 15;
        bSrc[it] = B + (size_t)kr * 1024 + nBase + qb * 8;
        bDst[it] = smem + 18432 + kr * 272 + qb * 16;
    }

    const int rl = lane & 7, sel = lane >> 3;
    const uint32_t aBase = smem + (wm * 64 + (sel & 1) * 8 + rl) * 144
                         + (sel >> 1) * 16;
    const uint32_t bBase = smem + 18432 + ((sel & 1) * 8 + rl) * 272
                         + (nOff + (sel >> 1) * 8) * 2;

    float d[4][8][4];
    #pragma unroll
    for (int f = 0; f < 4; ++f)
        #pragma unroll
        for (int g = 0; g < 8; ++g)
            #pragma unroll
            for (int j = 0; j < 4; ++j) d[f][g][j] = 0.f;

    auto issue = [&](int ch, uint32_t soff) {
        const int k0 = ch * 64;
        #pragma unroll
        for (int it = 0; it < 8; ++it)
            cp_async16(aDst[it] + soff, aSrc[it] + k0);
        #pragma unroll
        for (int it = 0; it < 8; ++it)
            cp_async16(bDst[it] + soff, bSrc[it] + (size_t)k0 * 1024);
        cp_commit();
    };

    issue(0, 0);
    issue(1, DN_STG);

    uint32_t cs = 0, ns = 2 * DN_STG;
    for (int ch = 0; ch < 16; ++ch) {
        if (ch < 15) cp_wait<1>(); else cp_wait<0>();
        __syncthreads();
        if (ch < 14) {
            issue(ch + 2, ns);
            ns = (ns == 2 * DN_STG) ? 0 : ns + DN_STG;
        }
        #pragma unroll
        for (int ks = 0; ks < 4; ++ks) {
            uint32_t af[4][4];
            #pragma unroll
            for (int f = 0; f < 4; ++f)
                ldsm_x4(af[f], aBase + cs + f * 2304 + ks * 32);
            uint32_t bf[4][4];
            #pragma unroll
            for (int g2 = 0; g2 < 4; ++g2)
                ldsm_x4t(bf[g2], bBase + cs + ks * 4352 + g2 * 32);
            #pragma unroll
            for (int f = 0; f < 4; ++f)
                #pragma unroll
                for (int g = 0; g < 8; ++g)
                    mma_f16(d[f][g], af[f], &bf[g >> 1][(g & 1) * 2]);
        }
        cs = (cs == 2 * DN_STG) ? 0 : cs + DN_STG;
    }

    #pragma unroll
    for (int f = 0; f < 4; ++f) {
        const int r = mBase + wm * 64 + f * 16 + row4;
        #pragma unroll
        for (int g = 0; g < 8; ++g) {
            const int c = nBase + nOff + g * 8 + kq * 2;
            *(float2*)(Out + (size_t)r * 1024 + c) =
                make_float2(d[f][g][0], d[f][g][1]);
            *(float2*)(Out + (size_t)(r + 8) * 1024 + c) =
                make_float2(d[f][g][2], d[f][g][3]);
        }
    }
}

// =============================================================================
// Final combine: out[t] = w0*Y[inv[2t]] + w1*Y[inv[2t+1]] + sigmoid(x.gw)*S[t]
// =============================================================================
__global__ void __launch_bounds__(256) combine_kernel(
    const float* __restrict__ X, const float* __restrict__ tw,
    const float* __restrict__ gw, float* __restrict__ out)
{
    const int t = blockIdx.x;
    const int tid = threadIdx.x;
    __shared__ float red[256];
    const float* xr = X + (size_t)t * 1024;
    float acc = 0.f;
    #pragma unroll
    for (int it = 0; it < 4; ++it) {
        const int dd = tid + it * 256;
        acc += xr[dd] * gw[dd];
    }
    red[tid] = acc;
    __syncthreads();
    for (int s = 128; s > 0; s >>= 1) {
        if (tid < s) red[tid] += red[tid + s];
        __syncthreads();
    }
    const float g = 1.f / (1.f + __expf(-red[0]));
    const int r0 = g_inv[2 * t], r1 = g_inv[2 * t + 1];
    const float w0 = tw[2 * t], w1 = tw[2 * t + 1];
    const float4 a = ((const float4*)(g_Y + (size_t)r0 * 1024))[tid];
    const float4 b = ((const float4*)(g_Y + (size_t)r1 * 1024))[tid];
    const float4 c = ((const float4*)(g_S + (size_t)t  * 1024))[tid];
    float4 r;
    r.x = w0 * a.x + w1 * b.x + g * c.x;
    r.y = w0 * a.y + w1 * b.y + g * c.y;
    r.z = w0 * a.z + w1 * b.z + g * c.z;
    r.w = w0 * a.w + w1 * b.w + g * c.w;
    ((float4*)(out + (size_t)t * 1024))[tid] = r;
}

// =============================================================================
extern "C" void kernel_launch(void* const* d_in, const int* in_sizes, int n_in,
                              void* d_out, int out_size) {
    (void)in_sizes; (void)n_in; (void)out_size;
    const float* X   = (const float*)d_in[0];
    const float* tw  = (const float*)d_in[1];
    const float* wg  = (const float*)d_in[2];
    const float* wu  = (const float*)d_in[3];
    const float* wd  = (const float*)d_in[4];
    const float* swg = (const float*)d_in[5];
    const float* swu = (const float*)d_in[6];
    const float* swd = (const float*)d_in[7];
    const float* gw  = (const float*)d_in[8];
    const int*   tki = (const int*)d_in[9];
    float* out = (float*)d_out;

    __half *hX, *hWg, *hWu, *hWd, *hSg, *hSu, *hSd, *H, *SH;
    float *Y, *S;
    cudaGetSymbolAddress((void**)&hX,  g_hX);
    cudaGetSymbolAddress((void**)&hWg, g_hwg);
    cudaGetSymbolAddress((void**)&hWu, g_hwu);
    cudaGetSymbolAddress((void**)&hWd, g_hwd);
    cudaGetSymbolAddress((void**)&hSg, g_hswg);
    cudaGetSymbolAddress((void**)&hSu, g_hswu);
    cudaGetSymbolAddress((void**)&hSd, g_hswd);
    cudaGetSymbolAddress((void**)&H,   g_H);
    cudaGetSymbolAddress((void**)&SH,  g_SH);
    cudaGetSymbolAddress((void**)&Y,   g_Y);
    cudaGetSymbolAddress((void**)&S,   g_S);

    cudaFuncSetAttribute(gemm_gu<true >, cudaFuncAttributeMaxDynamicSharedMemorySize, GU_SMEM);
    cudaFuncSetAttribute(gemm_gu<false>, cudaFuncAttributeMaxDynamicSharedMemorySize, GU_SMEM);
    cudaFuncSetAttribute(gemm_dn,        cudaFuncAttributeMaxDynamicSharedMemorySize, DN_SMEM);

    // 0. fp16 conversion + dispatch permutation
    cvt_all<<<1184, 256>>>(X, wg, wu, wd, swg, swu, swd);
    build_perm_kernel<<<NEXP, 256>>>(tki);
    // 1. routed gate+up fused -> H = fp16(silu(Xp@Wg) * (Xp@Wu))
    gemm_gu<true ><<<dim3(8, 16, NEXP), 256, GU_SMEM>>>(hX, hWg, hWu, H);
    // 2. routed down -> Y (fp32)
    gemm_dn<<<dim3(8, 8, NEXP), 128, DN_SMEM>>>(H, hWd, Y);
    // 3. shared gate+up fused -> SH
    gemm_gu<false><<<dim3(32, 16, 1), 256, GU_SMEM>>>(hX, hSg, hSu, SH);
    // 4. shared down -> S (fp32)
    gemm_dn<<<dim3(32, 8, 1), 128, DN_SMEM>>>(SH, hSd, S);
    // 5. combine
    combine_kernel<<<NTOK, 256>>>(X, tw, gw, out);
}

// round 8
// speedup vs baseline: 2.2872x; 1.0150x over previous
#include <cuda_runtime.h>
#include <cuda_fp16.h>
#include <cstdint>

// =============================================================================
// MoE fused layer, plain sm_103. R8: both GEMMs now 256-thr / warp tile 64x32
// (16 warps/SM). fp16 mma.sync m16n8k16, fp32 accum.
// T=4096, D=1024, E=8, K=2, F=SF=1024.
// =============================================================================

#define NEXP   8
#define NTOK   4096
#define NROWS  8192
#define CPE    1024

// ---------------- device-global scratch --------------------------------------
__device__ __align__(16) __half g_hX  [4096u * 1024u];
__device__ __align__(16) __half g_hwg [8u * 1024u * 1024u];
__device__ __align__(16) __half g_hwu [8u * 1024u * 1024u];
__device__ __align__(16) __half g_hwd [8u * 1024u * 1024u];
__device__ __align__(16) __half g_hswg[1024u * 1024u];
__device__ __align__(16) __half g_hswu[1024u * 1024u];
__device__ __align__(16) __half g_hswd[1024u * 1024u];
__device__ __align__(16) __half g_H [8192u * 1024u];
__device__ __align__(16) __half g_SH[4096u * 1024u];
__device__ float g_Y [8192u * 1024u];
__device__ float g_S [4096u * 1024u];
__device__ int   g_perm[8192];
__device__ int   g_inv [8192];

// ---------------- helpers ------------------------------------------------------
__device__ __forceinline__ uint32_t smem_u32(const void* p) {
    uint32_t a;
    asm("{ .reg .u64 t; cvta.to.shared.u64 t, %1; cvt.u32.u64 %0, t; }"
        : "=r"(a) : "l"(p));
    return a;
}
__device__ __forceinline__ void cp_async16(uint32_t dst, const void* src) {
    asm volatile("cp.async.cg.shared.global [%0], [%1], 16;"
                 :: "r"(dst), "l"(src) : "memory");
}
__device__ __forceinline__ void cp_commit() {
    asm volatile("cp.async.commit_group;" ::: "memory");
}
template<int N>
__device__ __forceinline__ void cp_wait() {
    asm volatile("cp.async.wait_group %0;" :: "n"(N) : "memory");
}
__device__ __forceinline__ void ldsm_x4(uint32_t* r, uint32_t addr) {
    asm volatile("ldmatrix.sync.aligned.m8n8.x4.shared.b16 {%0,%1,%2,%3}, [%4];"
                 : "=r"(r[0]), "=r"(r[1]), "=r"(r[2]), "=r"(r[3]) : "r"(addr));
}
__device__ __forceinline__ void ldsm_x4t(uint32_t* r, uint32_t addr) {
    asm volatile("ldmatrix.sync.aligned.m8n8.x4.trans.shared.b16 {%0,%1,%2,%3}, [%4];"
                 : "=r"(r[0]), "=r"(r[1]), "=r"(r[2]), "=r"(r[3]) : "r"(addr));
}
__device__ __forceinline__ void mma_f16(float* d, const uint32_t* a,
                                        const uint32_t* b) {
    asm volatile(
        "mma.sync.aligned.m16n8k16.row.col.f32.f16.f16.f32 "
        "{%0,%1,%2,%3}, {%4,%5,%6,%7}, {%8,%9}, {%0,%1,%2,%3};"
        : "+f"(d[0]), "+f"(d[1]), "+f"(d[2]), "+f"(d[3])
        : "r"(a[0]), "r"(a[1]), "r"(a[2]), "r"(a[3]), "r"(b[0]), "r"(b[1]));
}
__device__ __forceinline__ float silu(float x) {
    return x / (1.f + __expf(-x));
}

// =============================================================================
// fp32 -> fp16 conversion of all MMA inputs.
// =============================================================================
__global__ void __launch_bounds__(256) cvt_all(
    const float* __restrict__ x,
    const float* __restrict__ wg,  const float* __restrict__ wu,
    const float* __restrict__ wd,
    const float* __restrict__ swg, const float* __restrict__ swu,
    const float* __restrict__ swd)
{
    const size_t total = 8126464u;   // float4 units
    for (size_t i = (size_t)blockIdx.x * blockDim.x + threadIdx.x;
         i < total; i += (size_t)gridDim.x * blockDim.x) {
        const float4* s; __half2* d; size_t j;
        if      (i < 1048576u) { s = (const float4*)x;   d = (__half2*)g_hX;   j = i; }
        else if (i < 3145728u) { s = (const float4*)wg;  d = (__half2*)g_hwg;  j = i - 1048576u; }
        else if (i < 5242880u) { s = (const float4*)wu;  d = (__half2*)g_hwu;  j = i - 3145728u; }
        else if (i < 7340032u) { s = (const float4*)wd;  d = (__half2*)g_hwd;  j = i - 5242880u; }
        else if (i < 7602176u) { s = (const float4*)swg; d = (__half2*)g_hswg; j = i - 7340032u; }
        else if (i < 7864320u) { s = (const float4*)swu; d = (__half2*)g_hswu; j = i - 7602176u; }
        else                   { s = (const float4*)swd; d = (__half2*)g_hswd; j = i - 7864320u; }
        const float4 v = s[j];
        d[2 * j]     = __floats2half2_rn(v.x, v.y);
        d[2 * j + 1] = __floats2half2_rn(v.z, v.w);
    }
}

// =============================================================================
// Stable counting-sort permutation (matches jnp.argsort stability).
// =============================================================================
__global__ void build_perm_kernel(const int* __restrict__ tki) {
    const int e = blockIdx.x;
    const int tid = threadIdx.x;
    __shared__ int scan[256];
    __shared__ int basev;
    if (tid == 0) basev = 0;
    __syncthreads();
    for (int start = 0; start < NROWS; start += 256) {
        const int i = start + tid;
        const int m = (tki[i] == e) ? 1 : 0;
        scan[tid] = m;
        __syncthreads();
        #pragma unroll
        for (int off = 1; off < 256; off <<= 1) {
            int v = (tid >= off) ? scan[tid - off] : 0;
            __syncthreads();
            scan[tid] += v;
            __syncthreads();
        }
        if (m) {
            const int dest = e * CPE + basev + scan[tid] - 1;
            g_perm[dest] = i;
            g_inv[i] = dest;
        }
        __syncthreads();
        if (tid == 0) basev += scan[255];
        __syncthreads();
    }
}

// =============================================================================
// Fused gate+up GEMM (unchanged from R7 — known good).
// 256 thr, warps 0-3 gate / 4-7 up, warp tile 64x32, CTA 128m x 64n both mats.
// smem/stage: A 128*144 (18432) + 2 * 64*144 = 36864.
// =============================================================================
#define GU_STG   36864
#define GU_SMEM  (3 * GU_STG + 512)

template<bool GATHER>
__global__ void __launch_bounds__(256, 2) gemm_gu(
    const __half* __restrict__ A,
    const __half* __restrict__ B0g,
    const __half* __restrict__ B1g,
    __half* __restrict__ Out)
{
    extern __shared__ char sm[];
    const uint32_t smem = smem_u32(sm);
    int* srcRow = (int*)(sm + 3 * GU_STG);

    const int tid  = threadIdx.x;
    const int wid  = tid >> 5;
    const int lane = tid & 31;
    const int row4 = lane >> 2;
    const int kq   = lane & 3;
    const int rl   = lane & 7;
    const int sel  = lane >> 3;
    const int mat  = wid >> 2;
    const int wm   = (wid >> 1) & 1;
    const int wn2  = wid & 1;

    const int mBase = (blockIdx.z * gridDim.x + blockIdx.x) * 128;
    const int nBase = blockIdx.y * 64;

    if (tid < 128)
        srcRow[tid] = GATHER ? (g_perm[mBase + tid] >> 1) : (mBase + tid);
    __syncthreads();

    const __half* B0 = B0g + (size_t)blockIdx.z * 1048576u;
    const __half* B1 = B1g + (size_t)blockIdx.z * 1048576u;

    const __half* aSrc[4]; uint32_t aDst[4];
    const __half* bSrc[4]; uint32_t bDst[4];
    #pragma unroll
    for (int it = 0; it < 4; ++it) {
        const int ia = tid + it * 256;
        const int r = ia >> 3, q = ia & 7;
        aSrc[it] = A + (size_t)srcRow[r] * 1024 + q * 8;
        aDst[it] = smem + r * 144 + q * 16;
        const int mm = ia >> 9, kr = (ia >> 3) & 63, qb = ia & 7;
        bSrc[it] = (mm ? B1 : B0) + (size_t)kr * 1024 + nBase + qb * 8;
        bDst[it] = smem + 18432 + mm * 9216 + kr * 144 + qb * 16;
    }

    const uint32_t aBase = smem + (wm * 64 + (sel & 1) * 8 + rl) * 144
                         + (sel >> 1) * 16;
    const uint32_t bBase = smem + 18432 + mat * 9216
                         + ((sel & 1) * 8 + rl) * 144
                         + (wn2 * 32 + (sel >> 1) * 8) * 2;

    float d[4][4][4];
    #pragma unroll
    for (int f = 0; f < 4; ++f)
        #pragma unroll
        for (int g = 0; g < 4; ++g)
            #pragma unroll
            for (int j = 0; j < 4; ++j) d[f][g][j] = 0.f;

    auto issue = [&](int ch, uint32_t soff) {
        const int k0 = ch * 64;
        #pragma unroll
        for (int it = 0; it < 4; ++it)
            cp_async16(aDst[it] + soff, aSrc[it] + k0);
        #pragma unroll
        for (int it = 0; it < 4; ++it)
            cp_async16(bDst[it] + soff, bSrc[it] + (size_t)k0 * 1024);
        cp_commit();
    };

    issue(0, 0);
    issue(1, GU_STG);

    uint32_t cs = 0, ns = 2 * GU_STG;
    for (int ch = 0; ch < 16; ++ch) {
        if (ch < 15) cp_wait<1>(); else cp_wait<0>();
        __syncthreads();
        if (ch < 14) {
            issue(ch + 2, ns);
            ns = (ns == 2 * GU_STG) ? 0 : ns + GU_STG;
        }
        #pragma unroll
        for (int ks = 0; ks < 4; ++ks) {
            uint32_t af[4][4];
            #pragma unroll
            for (int f = 0; f < 4; ++f)
                ldsm_x4(af[f], aBase + cs + f * 2304 + ks * 32);
            uint32_t bf[2][4];
            #pragma unroll
            for (int g2 = 0; g2 < 2; ++g2)
                ldsm_x4t(bf[g2], bBase + cs + ks * 2304 + g2 * 32);
            #pragma unroll
            for (int f = 0; f < 4; ++f)
                #pragma unroll
                for (int g = 0; g < 4; ++g)
                    mma_f16(d[f][g], af[f], &bf[g >> 1][(g & 1) * 2]);
        }
        cs = (cs == 2 * GU_STG) ? 0 : cs + GU_STG;
    }

    __syncthreads();
    float* Us = (float*)sm;             // [128][66]
    if (mat == 1) {
        #pragma unroll
        for (int f = 0; f < 4; ++f) {
            const int r = wm * 64 + f * 16 + row4;
            #pragma unroll
            for (int g = 0; g < 4; ++g) {
                const int c = wn2 * 32 + g * 8 + kq * 2;
                *(float2*)(Us + r * 66 + c)       = make_float2(d[f][g][0], d[f][g][1]);
                *(float2*)(Us + (r + 8) * 66 + c) = make_float2(d[f][g][2], d[f][g][3]);
            }
        }
    }
    __syncthreads();
    if (mat == 0) {
        #pragma unroll
        for (int f = 0; f < 4; ++f) {
            const int r = wm * 64 + f * 16 + row4;
            #pragma unroll
            for (int g = 0; g < 4; ++g) {
                const int c = wn2 * 32 + g * 8 + kq * 2;
                const float2 u0 = *(const float2*)(Us + r * 66 + c);
                const float2 u1 = *(const float2*)(Us + (r + 8) * 66 + c);
                *(__half2*)(Out + (size_t)(mBase + r) * 1024 + nBase + c) =
                    __floats2half2_rn(silu(d[f][g][0]) * u0.x,
                                      silu(d[f][g][1]) * u0.y);
                *(__half2*)(Out + (size_t)(mBase + r + 8) * 1024 + nBase + c) =
                    __floats2half2_rn(silu(d[f][g][2]) * u1.x,
                                      silu(d[f][g][3]) * u1.y);
            }
        }
    }
}

// =============================================================================
// Down GEMM — R8: 256 thr, 8 warps (2m x 4n), warp tile 64x32, CTA 128x128.
// smem/stage: A 18432 + B 64*272 (17408) = 35840. 3 stages.
// =============================================================================
#define DN_STG   35840
#define DN_SMEM  (3 * DN_STG + 256)

__global__ void __launch_bounds__(256, 2) gemm_dn(
    const __half* __restrict__ A,
    const __half* __restrict__ Bg,
    float* __restrict__ Out)
{
    extern __shared__ char sm[];
    const uint32_t smem = smem_u32(sm);

    const int tid  = threadIdx.x;
    const int wid  = tid >> 5;
    const int lane = tid & 31;
    const int row4 = lane >> 2;
    const int kq   = lane & 3;
    const int rl   = lane & 7;
    const int sel  = lane >> 3;
    const int wm   = wid & 1;             // m half (64 rows)
    const int nOff = (wid >> 1) * 32;     // n quarter (32 cols)

    const int mBase = (blockIdx.z * gridDim.x + blockIdx.x) * 128;
    const int nBase = blockIdx.y * 128;

    const __half* B = Bg + (size_t)blockIdx.z * (1024u * 1024u);

    const __half* aSrc[4]; uint32_t aDst[4];
    const __half* bSrc[4]; uint32_t bDst[4];
    #pragma unroll
    for (int it = 0; it < 4; ++it) {
        const int ia = tid + it * 256;                   // 0..1023
        const int r = ia >> 3, q = ia & 7;               // A: 128 rows x 8 units
        aSrc[it] = A + (size_t)(mBase + r) * 1024 + q * 8;
        aDst[it] = smem + r * 144 + q * 16;
        const int kr = ia >> 4, qb = ia & 15;            // B: 64 rows x 16 units
        bSrc[it] = B + (size_t)kr * 1024 + nBase + qb * 8;
        bDst[it] = smem + 18432 + kr * 272 + qb * 16;
    }

    const uint32_t aBase = smem + (wm * 64 + (sel & 1) * 8 + rl) * 144
                         + (sel >> 1) * 16;
    const uint32_t bBase = smem + 18432 + ((sel & 1) * 8 + rl) * 272
                         + (nOff + (sel >> 1) * 8) * 2;

    float d[4][4][4];
    #pragma unroll
    for (int f = 0; f < 4; ++f)
        #pragma unroll
        for (int g = 0; g < 4; ++g)
            #pragma unroll
            for (int j = 0; j < 4; ++j) d[f][g][j] = 0.f;

    auto issue = [&](int ch, uint32_t soff) {
        const int k0 = ch * 64;
        #pragma unroll
        for (int it = 0; it < 4; ++it)
            cp_async16(aDst[it] + soff, aSrc[it] + k0);
        #pragma unroll
        for (int it = 0; it < 4; ++it)
            cp_async16(bDst[it] + soff, bSrc[it] + (size_t)k0 * 1024);
        cp_commit();
    };

    issue(0, 0);
    issue(1, DN_STG);

    uint32_t cs = 0, ns = 2 * DN_STG;
    for (int ch = 0; ch < 16; ++ch) {
        if (ch < 15) cp_wait<1>(); else cp_wait<0>();
        __syncthreads();
        if (ch < 14) {
            issue(ch + 2, ns);
            ns = (ns == 2 * DN_STG) ? 0 : ns + DN_STG;
        }
        #pragma unroll
        for (int ks = 0; ks < 4; ++ks) {
            uint32_t af[4][4];
            #pragma unroll
            for (int f = 0; f < 4; ++f)
                ldsm_x4(af[f], aBase + cs + f * 2304 + ks * 32);
            uint32_t bf[2][4];
            #pragma unroll
            for (int g2 = 0; g2 < 2; ++g2)
                ldsm_x4t(bf[g2], bBase + cs + ks * 4352 + g2 * 32);
            #pragma unroll
            for (int f = 0; f < 4; ++f)
                #pragma unroll
                for (int g = 0; g < 4; ++g)
                    mma_f16(d[f][g], af[f], &bf[g >> 1][(g & 1) * 2]);
        }
        cs = (cs == 2 * DN_STG) ? 0 : cs + DN_STG;
    }

    #pragma unroll
    for (int f = 0; f < 4; ++f) {
        const int r = mBase + wm * 64 + f * 16 + row4;
        #pragma unroll
        for (int g = 0; g < 4; ++g) {
            const int c = nBase + nOff + g * 8 + kq * 2;
            *(float2*)(Out + (size_t)r * 1024 + c) =
                make_float2(d[f][g][0], d[f][g][1]);
            *(float2*)(Out + (size_t)(r + 8) * 1024 + c) =
                make_float2(d[f][g][2], d[f][g][3]);
        }
    }
}

// =============================================================================
// Final combine: out[t] = w0*Y[inv[2t]] + w1*Y[inv[2t+1]] + sigmoid(x.gw)*S[t]
// =============================================================================
__global__ void __launch_bounds__(256) combine_kernel(
    const float* __restrict__ X, const float* __restrict__ tw,
    const float* __restrict__ gw, float* __restrict__ out)
{
    const int t = blockIdx.x;
    const int tid = threadIdx.x;
    __shared__ float red[256];
    const float* xr = X + (size_t)t * 1024;
    float acc = 0.f;
    #pragma unroll
    for (int it = 0; it < 4; ++it) {
        const int dd = tid + it * 256;
        acc += xr[dd] * gw[dd];
    }
    red[tid] = acc;
    __syncthreads();
    for (int s = 128; s > 0; s >>= 1) {
        if (tid < s) red[tid] += red[tid + s];
        __syncthreads();
    }
    const float g = 1.f / (1.f + __expf(-red[0]));
    const int r0 = g_inv[2 * t], r1 = g_inv[2 * t + 1];
    const float w0 = tw[2 * t], w1 = tw[2 * t + 1];
    const float4 a = ((const float4*)(g_Y + (size_t)r0 * 1024))[tid];
    const float4 b = ((const float4*)(g_Y + (size_t)r1 * 1024))[tid];
    const float4 c = ((const float4*)(g_S + (size_t)t  * 1024))[tid];
    float4 r;
    r.x = w0 * a.x + w1 * b.x + g * c.x;
    r.y = w0 * a.y + w1 * b.y + g * c.y;
    r.z = w0 * a.z + w1 * b.z + g * c.z;
    r.w = w0 * a.w + w1 * b.w + g * c.w;
    ((float4*)(out + (size_t)t * 1024))[tid] = r;
}

// =============================================================================
extern "C" void kernel_launch(void* const* d_in, const int* in_sizes, int n_in,
                              void* d_out, int out_size) {
    (void)in_sizes; (void)n_in; (void)out_size;
    const float* X   = (const float*)d_in[0];
    const float* tw  = (const float*)d_in[1];
    const float* wg  = (const float*)d_in[2];
    const float* wu  = (const float*)d_in[3];
    const float* wd  = (const float*)d_in[4];
    const float* swg = (const float*)d_in[5];
    const float* swu = (const float*)d_in[6];
    const float* swd = (const float*)d_in[7];
    const float* gw  = (const float*)d_in[8];
    const int*   tki = (const int*)d_in[9];
    float* out = (float*)d_out;

    __half *hX, *hWg, *hWu, *hWd, *hSg, *hSu, *hSd, *H, *SH;
    float *Y, *S;
    cudaGetSymbolAddress((void**)&hX,  g_hX);
    cudaGetSymbolAddress((void**)&hWg, g_hwg);
    cudaGetSymbolAddress((void**)&hWu, g_hwu);
    cudaGetSymbolAddress((void**)&hWd, g_hwd);
    cudaGetSymbolAddress((void**)&hSg, g_hswg);
    cudaGetSymbolAddress((void**)&hSu, g_hswu);
    cudaGetSymbolAddress((void**)&hSd, g_hswd);
    cudaGetSymbolAddress((void**)&H,   g_H);
    cudaGetSymbolAddress((void**)&SH,  g_SH);
    cudaGetSymbolAddress((void**)&Y,   g_Y);
    cudaGetSymbolAddress((void**)&S,   g_S);

    cudaFuncSetAttribute(gemm_gu<true >, cudaFuncAttributeMaxDynamicSharedMemorySize, GU_SMEM);
    cudaFuncSetAttribute(gemm_gu<false>, cudaFuncAttributeMaxDynamicSharedMemorySize, GU_SMEM);
    cudaFuncSetAttribute(gemm_dn,        cudaFuncAttributeMaxDynamicSharedMemorySize, DN_SMEM);

    // 0. fp16 conversion + dispatch permutation
    cvt_all<<<1184, 256>>>(X, wg, wu, wd, swg, swu, swd);
    build_perm_kernel<<<NEXP, 256>>>(tki);
    // 1. routed gate+up fused -> H = fp16(silu(Xp@Wg) * (Xp@Wu))
    gemm_gu<true ><<<dim3(8, 16, NEXP), 256, GU_SMEM>>>(hX, hWg, hWu, H);
    // 2. routed down -> Y (fp32)
    gemm_dn<<<dim3(8, 8, NEXP), 256, DN_SMEM>>>(H, hWd, Y);
    // 3. shared gate+up fused -> SH
    gemm_gu<false><<<dim3(32, 16, 1), 256, GU_SMEM>>>(hX, hSg, hSu, SH);
    // 4. shared down -> S (fp32)
    gemm_dn<<<dim3(32, 8, 1), 256, DN_SMEM>>>(SH, hSd, S);
    // 5. combine
    combine_kernel<<<NTOK, 256>>>(X, tw, gw, out);
}

// round 9
// speedup vs baseline: 2.7348x; 1.1957x over previous
#include <cuda_runtime.h>
#include <cuda_fp16.h>
#include <cstdint>

// =============================================================================
// MoE fused layer, plain sm_103. R9: R8 GEMMs unchanged; orchestration now
// fork-join two-stream capture (routed chain || shared chain, perm || cvt);
// ballot-based permutation; shuffle-reduction combine.
// T=4096, D=1024, E=8, K=2, F=SF=1024.
// =============================================================================

#define NEXP   8
#define NTOK   4096
#define NROWS  8192
#define CPE    1024

// ---------------- device-global scratch --------------------------------------
__device__ __align__(16) __half g_hX  [4096u * 1024u];
__device__ __align__(16) __half g_hwg [8u * 1024u * 1024u];
__device__ __align__(16) __half g_hwu [8u * 1024u * 1024u];
__device__ __align__(16) __half g_hwd [8u * 1024u * 1024u];
__device__ __align__(16) __half g_hswg[1024u * 1024u];
__device__ __align__(16) __half g_hswu[1024u * 1024u];
__device__ __align__(16) __half g_hswd[1024u * 1024u];
__device__ __align__(16) __half g_H [8192u * 1024u];
__device__ __align__(16) __half g_SH[4096u * 1024u];
__device__ float g_Y [8192u * 1024u];
__device__ float g_S [4096u * 1024u];
__device__ int   g_perm[8192];
__device__ int   g_inv [8192];

// ---------------- helpers ------------------------------------------------------
__device__ __forceinline__ uint32_t smem_u32(const void* p) {
    uint32_t a;
    asm("{ .reg .u64 t; cvta.to.shared.u64 t, %1; cvt.u32.u64 %0, t; }"
        : "=r"(a) : "l"(p));
    return a;
}
__device__ __forceinline__ void cp_async16(uint32_t dst, const void* src) {
    asm volatile("cp.async.cg.shared.global [%0], [%1], 16;"
                 :: "r"(dst), "l"(src) : "memory");
}
__device__ __forceinline__ void cp_commit() {
    asm volatile("cp.async.commit_group;" ::: "memory");
}
template<int N>
__device__ __forceinline__ void cp_wait() {
    asm volatile("cp.async.wait_group %0;" :: "n"(N) : "memory");
}
__device__ __forceinline__ void ldsm_x4(uint32_t* r, uint32_t addr) {
    asm volatile("ldmatrix.sync.aligned.m8n8.x4.shared.b16 {%0,%1,%2,%3}, [%4];"
                 : "=r"(r[0]), "=r"(r[1]), "=r"(r[2]), "=r"(r[3]) : "r"(addr));
}
__device__ __forceinline__ void ldsm_x4t(uint32_t* r, uint32_t addr) {
    asm volatile("ldmatrix.sync.aligned.m8n8.x4.trans.shared.b16 {%0,%1,%2,%3}, [%4];"
                 : "=r"(r[0]), "=r"(r[1]), "=r"(r[2]), "=r"(r[3]) : "r"(addr));
}
__device__ __forceinline__ void mma_f16(float* d, const uint32_t* a,
                                        const uint32_t* b) {
    asm volatile(
        "mma.sync.aligned.m16n8k16.row.col.f32.f16.f16.f32 "
        "{%0,%1,%2,%3}, {%4,%5,%6,%7}, {%8,%9}, {%0,%1,%2,%3};"
        : "+f"(d[0]), "+f"(d[1]), "+f"(d[2]), "+f"(d[3])
        : "r"(a[0]), "r"(a[1]), "r"(a[2]), "r"(a[3]), "r"(b[0]), "r"(b[1]));
}
__device__ __forceinline__ float silu(float x) {
    return x / (1.f + __expf(-x));
}

// =============================================================================
// fp32 -> fp16 conversion of all MMA inputs.
// =============================================================================
__global__ void __launch_bounds__(256) cvt_all(
    const float* __restrict__ x,
    const float* __restrict__ wg,  const float* __restrict__ wu,
    const float* __restrict__ wd,
    const float* __restrict__ swg, const float* __restrict__ swu,
    const float* __restrict__ swd)
{
    const size_t total = 8126464u;   // float4 units
    for (size_t i = (size_t)blockIdx.x * blockDim.x + threadIdx.x;
         i < total; i += (size_t)gridDim.x * blockDim.x) {
        const float4* s; __half2* d; size_t j;
        if      (i < 1048576u) { s = (const float4*)x;   d = (__half2*)g_hX;   j = i; }
        else if (i < 3145728u) { s = (const float4*)wg;  d = (__half2*)g_hwg;  j = i - 1048576u; }
        else if (i < 5242880u) { s = (const float4*)wu;  d = (__half2*)g_hwu;  j = i - 3145728u; }
        else if (i < 7340032u) { s = (const float4*)wd;  d = (__half2*)g_hwd;  j = i - 5242880u; }
        else if (i < 7602176u) { s = (const float4*)swg; d = (__half2*)g_hswg; j = i - 7340032u; }
        else if (i < 7864320u) { s = (const float4*)swu; d = (__half2*)g_hswu; j = i - 7602176u; }
        else                   { s = (const float4*)swd; d = (__half2*)g_hswd; j = i - 7864320u; }
        const float4 v = s[j];
        d[2 * j]     = __floats2half2_rn(v.x, v.y);
        d[2 * j + 1] = __floats2half2_rn(v.z, v.w);
    }
}

// =============================================================================
// Stable counting-sort permutation via warp ballots (matches jnp.argsort
// stability: within expert e, flat indices appear in increasing order).
// =============================================================================
__global__ void build_perm_kernel(const int* __restrict__ tki) {
    const int e    = blockIdx.x;
    const int tid  = threadIdx.x;
    const int lane = tid & 31;
    const int w    = tid >> 5;
    __shared__ int wcnt[8];
    __shared__ int basev;
    if (tid == 0) basev = 0;
    __syncthreads();
    for (int start = 0; start < NROWS; start += 256) {
        const int i = start + tid;
        const bool m = (tki[i] == e);
        const uint32_t mask = __ballot_sync(0xffffffffu, m);
        if (lane == 0) wcnt[w] = __popc(mask);
        __syncthreads();
        int wpre = 0, tot = 0;
        #pragma unroll
        for (int ww = 0; ww < 8; ++ww) {
            const int c = wcnt[ww];
            wpre += (ww < w) ? c : 0;
            tot  += c;
        }
        if (m) {
            const int rank = __popc(mask & ((1u << lane) - 1u));
            const int dest = e * CPE + basev + wpre + rank;
            g_perm[dest] = i;
            g_inv[i] = dest;
        }
        __syncthreads();
        if (tid == 0) basev += tot;
        __syncthreads();
    }
}

// =============================================================================
// Fused gate+up GEMM (R8 verbatim — known good).
// =============================================================================
#define GU_STG   36864
#define GU_SMEM  (3 * GU_STG + 512)

template<bool GATHER>
__global__ void __launch_bounds__(256, 2) gemm_gu(
    const __half* __restrict__ A,
    const __half* __restrict__ B0g,
    const __half* __restrict__ B1g,
    __half* __restrict__ Out)
{
    extern __shared__ char sm[];
    const uint32_t smem = smem_u32(sm);
    int* srcRow = (int*)(sm + 3 * GU_STG);

    const int tid  = threadIdx.x;
    const int wid  = tid >> 5;
    const int lane = tid & 31;
    const int row4 = lane >> 2;
    const int kq   = lane & 3;
    const int rl   = lane & 7;
    const int sel  = lane >> 3;
    const int mat  = wid >> 2;
    const int wm   = (wid >> 1) & 1;
    const int wn2  = wid & 1;

    const int mBase = (blockIdx.z * gridDim.x + blockIdx.x) * 128;
    const int nBase = blockIdx.y * 64;

    if (tid < 128)
        srcRow[tid] = GATHER ? (g_perm[mBase + tid] >> 1) : (mBase + tid);
    __syncthreads();

    const __half* B0 = B0g + (size_t)blockIdx.z * 1048576u;
    const __half* B1 = B1g + (size_t)blockIdx.z * 1048576u;

    const __half* aSrc[4]; uint32_t aDst[4];
    const __half* bSrc[4]; uint32_t bDst[4];
    #pragma unroll
    for (int it = 0; it < 4; ++it) {
        const int ia = tid + it * 256;
        const int r = ia >> 3, q = ia & 7;
        aSrc[it] = A + (size_t)srcRow[r] * 1024 + q * 8;
        aDst[it] = smem + r * 144 + q * 16;
        const int mm = ia >> 9, kr = (ia >> 3) & 63, qb = ia & 7;
        bSrc[it] = (mm ? B1 : B0) + (size_t)kr * 1024 + nBase + qb * 8;
        bDst[it] = smem + 18432 + mm * 9216 + kr * 144 + qb * 16;
    }

    const uint32_t aBase = smem + (wm * 64 + (sel & 1) * 8 + rl) * 144
                         + (sel >> 1) * 16;
    const uint32_t bBase = smem + 18432 + mat * 9216
                         + ((sel & 1) * 8 + rl) * 144
                         + (wn2 * 32 + (sel >> 1) * 8) * 2;

    float d[4][4][4];
    #pragma unroll
    for (int f = 0; f < 4; ++f)
        #pragma unroll
        for (int g = 0; g < 4; ++g)
            #pragma unroll
            for (int j = 0; j < 4; ++j) d[f][g][j] = 0.f;

    auto issue = [&](int ch, uint32_t soff) {
        const int k0 = ch * 64;
        #pragma unroll
        for (int it = 0; it < 4; ++it)
            cp_async16(aDst[it] + soff, aSrc[it] + k0);
        #pragma unroll
        for (int it = 0; it < 4; ++it)
            cp_async16(bDst[it] + soff, bSrc[it] + (size_t)k0 * 1024);
        cp_commit();
    };

    issue(0, 0);
    issue(1, GU_STG);

    uint32_t cs = 0, ns = 2 * GU_STG;
    for (int ch = 0; ch < 16; ++ch) {
        if (ch < 15) cp_wait<1>(); else cp_wait<0>();
        __syncthreads();
        if (ch < 14) {
            issue(ch + 2, ns);
            ns = (ns == 2 * GU_STG) ? 0 : ns + GU_STG;
        }
        #pragma unroll
        for (int ks = 0; ks < 4; ++ks) {
            uint32_t af[4][4];
            #pragma unroll
            for (int f = 0; f < 4; ++f)
                ldsm_x4(af[f], aBase + cs + f * 2304 + ks * 32);
            uint32_t bf[2][4];
            #pragma unroll
            for (int g2 = 0; g2 < 2; ++g2)
                ldsm_x4t(bf[g2], bBase + cs + ks * 2304 + g2 * 32);
            #pragma unroll
            for (int f = 0; f < 4; ++f)
                #pragma unroll
                for (int g = 0; g < 4; ++g)
                    mma_f16(d[f][g], af[f], &bf[g >> 1][(g & 1) * 2]);
        }
        cs = (cs == 2 * GU_STG) ? 0 : cs + GU_STG;
    }

    __syncthreads();
    float* Us = (float*)sm;             // [128][66]
    if (mat == 1) {
        #pragma unroll
        for (int f = 0; f < 4; ++f) {
            const int r = wm * 64 + f * 16 + row4;
            #pragma unroll
            for (int g = 0; g < 4; ++g) {
                const int c = wn2 * 32 + g * 8 + kq * 2;
                *(float2*)(Us + r * 66 + c)       = make_float2(d[f][g][0], d[f][g][1]);
                *(float2*)(Us + (r + 8) * 66 + c) = make_float2(d[f][g][2], d[f][g][3]);
            }
        }
    }
    __syncthreads();
    if (mat == 0) {
        #pragma unroll
        for (int f = 0; f < 4; ++f) {
            const int r = wm * 64 + f * 16 + row4;
            #pragma unroll
            for (int g = 0; g < 4; ++g) {
                const int c = wn2 * 32 + g * 8 + kq * 2;
                const float2 u0 = *(const float2*)(Us + r * 66 + c);
                const float2 u1 = *(const float2*)(Us + (r + 8) * 66 + c);
                *(__half2*)(Out + (size_t)(mBase + r) * 1024 + nBase + c) =
                    __floats2half2_rn(silu(d[f][g][0]) * u0.x,
                                      silu(d[f][g][1]) * u0.y);
                *(__half2*)(Out + (size_t)(mBase + r + 8) * 1024 + nBase + c) =
                    __floats2half2_rn(silu(d[f][g][2]) * u1.x,
                                      silu(d[f][g][3]) * u1.y);
            }
        }
    }
}

// =============================================================================
// Down GEMM (R8 verbatim — known good).
// =============================================================================
#define DN_STG   35840
#define DN_SMEM  (3 * DN_STG + 256)

__global__ void __launch_bounds__(256, 2) gemm_dn(
    const __half* __restrict__ A,
    const __half* __restrict__ Bg,
    float* __restrict__ Out)
{
    extern __shared__ char sm[];
    const uint32_t smem = smem_u32(sm);

    const int tid  = threadIdx.x;
    const int wid  = tid >> 5;
    const int lane = tid & 31;
    const int row4 = lane >> 2;
    const int kq   = lane & 3;
    const int rl   = lane & 7;
    const int sel  = lane >> 3;
    const int wm   = wid & 1;
    const int nOff = (wid >> 1) * 32;

    const int mBase = (blockIdx.z * gridDim.x + blockIdx.x) * 128;
    const int nBase = blockIdx.y * 128;

    const __half* B = Bg + (size_t)blockIdx.z * (1024u * 1024u);

    const __half* aSrc[4]; uint32_t aDst[4];
    const __half* bSrc[4]; uint32_t bDst[4];
    #pragma unroll
    for (int it = 0; it < 4; ++it) {
        const int ia = tid + it * 256;
        const int r = ia >> 3, q = ia & 7;
        aSrc[it] = A + (size_t)(mBase + r) * 1024 + q * 8;
        aDst[it] = smem + r * 144 + q * 16;
        const int kr = ia >> 4, qb = ia & 15;
        bSrc[it] = B + (size_t)kr * 1024 + nBase + qb * 8;
        bDst[it] = smem + 18432 + kr * 272 + qb * 16;
    }

    const uint32_t aBase = smem + (wm * 64 + (sel & 1) * 8 + rl) * 144
                         + (sel >> 1) * 16;
    const uint32_t bBase = smem + 18432 + ((sel & 1) * 8 + rl) * 272
                         + (nOff + (sel >> 1) * 8) * 2;

    float d[4][4][4];
    #pragma unroll
    for (int f = 0; f < 4; ++f)
        #pragma unroll
        for (int g = 0; g < 4; ++g)
            #pragma unroll
            for (int j = 0; j < 4; ++j) d[f][g][j] = 0.f;

    auto issue = [&](int ch, uint32_t soff) {
        const int k0 = ch * 64;
        #pragma unroll
        for (int it = 0; it < 4; ++it)
            cp_async16(aDst[it] + soff, aSrc[it] + k0);
        #pragma unroll
        for (int it = 0; it < 4; ++it)
            cp_async16(bDst[it] + soff, bSrc[it] + (size_t)k0 * 1024);
        cp_commit();
    };

    issue(0, 0);
    issue(1, DN_STG);

    uint32_t cs = 0, ns = 2 * DN_STG;
    for (int ch = 0; ch < 16; ++ch) {
        if (ch < 15) cp_wait<1>(); else cp_wait<0>();
        __syncthreads();
        if (ch < 14) {
            issue(ch + 2, ns);
            ns = (ns == 2 * DN_STG) ? 0 : ns + DN_STG;
        }
        #pragma unroll
        for (int ks = 0; ks < 4; ++ks) {
            uint32_t af[4][4];
            #pragma unroll
            for (int f = 0; f < 4; ++f)
                ldsm_x4(af[f], aBase + cs + f * 2304 + ks * 32);
            uint32_t bf[2][4];
            #pragma unroll
            for (int g2 = 0; g2 < 2; ++g2)
                ldsm_x4t(bf[g2], bBase + cs + ks * 4352 + g2 * 32);
            #pragma unroll
            for (int f = 0; f < 4; ++f)
                #pragma unroll
                for (int g = 0; g < 4; ++g)
                    mma_f16(d[f][g], af[f], &bf[g >> 1][(g & 1) * 2]);
        }
        cs = (cs == 2 * DN_STG) ? 0 : cs + DN_STG;
    }

    #pragma unroll
    for (int f = 0; f < 4; ++f) {
        const int r = mBase + wm * 64 + f * 16 + row4;
        #pragma unroll
        for (int g = 0; g < 4; ++g) {
            const int c = nBase + nOff + g * 8 + kq * 2;
            *(float2*)(Out + (size_t)r * 1024 + c) =
                make_float2(d[f][g][0], d[f][g][1]);
            *(float2*)(Out + (size_t)(r + 8) * 1024 + c) =
                make_float2(d[f][g][2], d[f][g][3]);
        }
    }
}

// =============================================================================
// Final combine (shuffle reduction):
// out[t] = w0*Y[inv[2t]] + w1*Y[inv[2t+1]] + sigmoid(x.gw)*S[t]
// =============================================================================
__global__ void __launch_bounds__(256) combine_kernel(
    const float* __restrict__ X, const float* __restrict__ tw,
    const float* __restrict__ gw, float* __restrict__ out)
{
    const int t = blockIdx.x;
    const int tid = threadIdx.x;
    const int lane = tid & 31, w = tid >> 5;
    __shared__ float wsum[8];

    const float4 xv = ((const float4*)(X + (size_t)t * 1024))[tid];
    const float4 gv = ((const float4*)gw)[tid];
    float acc = xv.x * gv.x + xv.y * gv.y + xv.z * gv.z + xv.w * gv.w;
    #pragma unroll
    for (int o = 16; o; o >>= 1)
        acc += __shfl_xor_sync(0xffffffffu, acc, o);
    if (lane == 0) wsum[w] = acc;
    __syncthreads();
    float tot = 0.f;
    #pragma unroll
    for (int ww = 0; ww < 8; ++ww) tot += wsum[ww];

    const float g = 1.f / (1.f + __expf(-tot));
    const int r0 = g_inv[2 * t], r1 = g_inv[2 * t + 1];
    const float w0 = tw[2 * t], w1 = tw[2 * t + 1];
    const float4 a = ((const float4*)(g_Y + (size_t)r0 * 1024))[tid];
    const float4 b = ((const float4*)(g_Y + (size_t)r1 * 1024))[tid];
    const float4 c = ((const float4*)(g_S + (size_t)t  * 1024))[tid];
    float4 r;
    r.x = w0 * a.x + w1 * b.x + g * c.x;
    r.y = w0 * a.y + w1 * b.y + g * c.y;
    r.z = w0 * a.z + w1 * b.z + g * c.z;
    r.w = w0 * a.w + w1 * b.w + g * c.w;
    ((float4*)(out + (size_t)t * 1024))[tid] = r;
}

// =============================================================================
extern "C" void kernel_launch(void* const* d_in, const int* in_sizes, int n_in,
                              void* d_out, int out_size) {
    (void)in_sizes; (void)n_in; (void)out_size;
    const float* X   = (const float*)d_in[0];
    const float* tw  = (const float*)d_in[1];
    const float* wg  = (const float*)d_in[2];
    const float* wu  = (const float*)d_in[3];
    const float* wd  = (const float*)d_in[4];
    const float* swg = (const float*)d_in[5];
    const float* swu = (const float*)d_in[6];
    const float* swd = (const float*)d_in[7];
    const float* gw  = (const float*)d_in[8];
    const int*   tki = (const int*)d_in[9];
    float* out = (float*)d_out;

    __half *hX, *hWg, *hWu, *hWd, *hSg, *hSu, *hSd, *H, *SH;
    float *Y, *S;
    cudaGetSymbolAddress((void**)&hX,  g_hX);
    cudaGetSymbolAddress((void**)&hWg, g_hwg);
    cudaGetSymbolAddress((void**)&hWu, g_hwu);
    cudaGetSymbolAddress((void**)&hWd, g_hwd);
    cudaGetSymbolAddress((void**)&hSg, g_hswg);
    cudaGetSymbolAddress((void**)&hSu, g_hswu);
    cudaGetSymbolAddress((void**)&hSd, g_hswd);
    cudaGetSymbolAddress((void**)&H,   g_H);
    cudaGetSymbolAddress((void**)&SH,  g_SH);
    cudaGetSymbolAddress((void**)&Y,   g_Y);
    cudaGetSymbolAddress((void**)&S,   g_S);

    // one-time (uncaptured first call) stream/event creation — no device allocs
    static cudaStream_t s1 = nullptr;
    static cudaEvent_t evStart = nullptr, evCvt = nullptr,
                       evPerm = nullptr, evShared = nullptr;
    if (!s1) {
        cudaStreamCreateWithFlags(&s1, cudaStreamNonBlocking);
        cudaEventCreateWithFlags(&evStart,  cudaEventDisableTiming);
        cudaEventCreateWithFlags(&evCvt,    cudaEventDisableTiming);
        cudaEventCreateWithFlags(&evPerm,   cudaEventDisableTiming);
        cudaEventCreateWithFlags(&evShared, cudaEventDisableTiming);
        cudaFuncSetAttribute(gemm_gu<true >, cudaFuncAttributeMaxDynamicSharedMemorySize, GU_SMEM);
        cudaFuncSetAttribute(gemm_gu<false>, cudaFuncAttributeMaxDynamicSharedMemorySize, GU_SMEM);
        cudaFuncSetAttribute(gemm_dn,        cudaFuncAttributeMaxDynamicSharedMemorySize, DN_SMEM);
    }

    // ---- stream 0 (captured origin): cvt -------------------------------------
    cudaEventRecord(evStart, 0);
    cvt_all<<<2368, 256>>>(X, wg, wu, wd, swg, swu, swd);
    cudaEventRecord(evCvt, 0);

    // ---- stream s1: perm (|| cvt), then shared chain (after cvt) -------------
    cudaStreamWaitEvent(s1, evStart, 0);
    build_perm_kernel<<<NEXP, 256, 0, s1>>>(tki);
    cudaEventRecord(evPerm, s1);
    cudaStreamWaitEvent(s1, evCvt, 0);
    gemm_gu<false><<<dim3(32, 16, 1), 256, GU_SMEM, s1>>>(hX, hSg, hSu, SH);
    gemm_dn<<<dim3(32, 8, 1), 256, DN_SMEM, s1>>>(SH, hSd, S);
    cudaEventRecord(evShared, s1);

    // ---- stream 0: routed chain, then join + combine -------------------------
    cudaStreamWaitEvent(0, evPerm, 0);
    gemm_gu<true ><<<dim3(8, 16, NEXP), 256, GU_SMEM>>>(hX, hWg, hWu, H);
    gemm_dn<<<dim3(8, 8, NEXP), 256, DN_SMEM>>>(H, hWd, Y);
    cudaStreamWaitEvent(0, evShared, 0);
    combine_kernel<<<NTOK, 256>>>(X, tw, gw, out);
}